// round 5
// baseline (speedup 1.0000x reference)
#include <cuda_runtime.h>
#include <cuda_bf16.h>
#include <math.h>
#include <stdint.h>

#define L 4096
#define DM 1024
#define DIN 2048
#define NH 32
#define HD 64
#define NST 128
#define CONVD 2560
#define DPROJ 4672
#define CHK 128
#define NC 32
#define EPSV 1e-5f

// ---------------- scratch (static device globals; no allocation) ----------------
__device__ float g_zx[(size_t)L * DPROJ];        // in_proj output (4096 x 4672)
__device__ float g_xc[(size_t)L * CONVD];        // conv+silu output (x_og | BC)
__device__ float g_dt2[2 * L * NH];              // softplus dt, both dirs
__device__ float g_Bm[(size_t)2 * L * NST];      // B per dir (flipped for dir1)
__device__ float g_Cm[(size_t)2 * L * NST];      // C per dir
__device__ float g_xdt[(size_t)2 * L * DIN];     // x (flipped) * dt
__device__ float g_Acs[2 * NC * NH * CHK];       // per-chunk cumsum of A*dt
__device__ float g_G[(size_t)2 * NC * CHK * CHK];// C B^T per (dir,chunk)
__device__ float g_Yd[(size_t)2 * L * DIN];      // Y (diag then += off + x*D)
__device__ float g_states[(size_t)2 * NC * NH * NST * HD]; // [n][p] layout per block
__device__ float g_fd[L * NH];

// bf16 hi/lo split buffers for tensor-core GEMMs
__device__ __align__(16) __nv_bfloat16 g_uh[(size_t)L * DM];
__device__ __align__(16) __nv_bfloat16 g_ul[(size_t)L * DM];
__device__ __align__(16) __nv_bfloat16 g_wih[(size_t)DPROJ * DM];
__device__ __align__(16) __nv_bfloat16 g_wil[(size_t)DPROJ * DM];
__device__ __align__(16) __nv_bfloat16 g_ynh[(size_t)L * DIN];
__device__ __align__(16) __nv_bfloat16 g_ynl[(size_t)L * DIN];
__device__ __align__(16) __nv_bfloat16 g_woh[(size_t)DM * DIN];
__device__ __align__(16) __nv_bfloat16 g_wol[(size_t)DM * DIN];

__device__ __forceinline__ float sigmoidf_(float x) { return 1.f / (1.f + expf(-x)); }

__device__ __forceinline__ uint32_t smem_u32(const void* p) {
    uint32_t a;
    asm("{ .reg .u64 tmp; cvta.to.shared.u64 tmp, %1; cvt.u32.u64 %0, tmp; }" : "=r"(a) : "l"(p));
    return a;
}
__device__ __forceinline__ void cp_async16(uint32_t dst, const void* src, int srcsize) {
    asm volatile("cp.async.cg.shared.global [%0], [%1], 16, %2;"
                 :: "r"(dst), "l"(src), "r"(srcsize));
}
#define CP_COMMIT() asm volatile("cp.async.commit_group;" ::: "memory")
#define CP_WAIT1()  asm volatile("cp.async.wait_group 1;"  ::: "memory")
#define CP_WAIT0()  asm volatile("cp.async.wait_group 0;"  ::: "memory")

__device__ __forceinline__ void ldsm4(uint32_t* r, uint32_t addr) {
    asm volatile("ldmatrix.sync.aligned.m8n8.x4.shared.b16 {%0,%1,%2,%3}, [%4];"
                 : "=r"(r[0]), "=r"(r[1]), "=r"(r[2]), "=r"(r[3]) : "r"(addr));
}
__device__ __forceinline__ void ldsm4t(uint32_t* r, uint32_t addr) {
    asm volatile("ldmatrix.sync.aligned.m8n8.x4.trans.shared.b16 {%0,%1,%2,%3}, [%4];"
                 : "=r"(r[0]), "=r"(r[1]), "=r"(r[2]), "=r"(r[3]) : "r"(addr));
}
__device__ __forceinline__ void mma16816(float* c, const uint32_t* a, uint32_t b0, uint32_t b1) {
    asm volatile("mma.sync.aligned.m16n8k16.row.col.f32.bf16.bf16.f32 "
                 "{%0,%1,%2,%3}, {%4,%5,%6,%7}, {%8,%9}, {%0,%1,%2,%3};"
                 : "+f"(c[0]), "+f"(c[1]), "+f"(c[2]), "+f"(c[3])
                 : "r"(a[0]), "r"(a[1]), "r"(a[2]), "r"(a[3]), "r"(b0), "r"(b1));
}
__device__ __forceinline__ void split_hilo(float v, __nv_bfloat16& h, __nv_bfloat16& l) {
    h = __float2bfloat16(v);
    l = __float2bfloat16(v - __bfloat162float(h));
}

// ---------------- fp32 -> bf16 hi/lo split ----------------
__global__ void cvt_hilo_kernel(const float* __restrict__ x,
                                __nv_bfloat16* __restrict__ hi,
                                __nv_bfloat16* __restrict__ lo, size_t n) {
    size_t i = (size_t)blockIdx.x * blockDim.x + threadIdx.x;
    if (i >= n) return;
    __nv_bfloat16 h, lv;
    split_hilo(x[i], h, lv);
    hi[i] = h; lo[i] = lv;
}

// ============ mma.sync bf16 hi/lo-split GEMM: C[m,n] = sum_k A[m,k]*B[n,k] ============
#define KC 32
#define APAD 40   // smem row stride in bf16 (80B, ldmatrix conflict-free)

__global__ __launch_bounds__(256, 2) void gemm_mma(
    const __nv_bfloat16* __restrict__ Ah, const __nv_bfloat16* __restrict__ Al,
    const __nv_bfloat16* __restrict__ Bh, const __nv_bfloat16* __restrict__ Bl,
    float* __restrict__ Cc, int Ntot, int Ktot) {
    extern __shared__ __align__(16) __nv_bfloat16 sm[];
    const int tid = threadIdx.x;
    const int bRow = blockIdx.y * 128, bCol = blockIdx.x * 128;
    const int wid = tid >> 5, lane = tid & 31;
    const int wm = (wid >> 2) * 64, wn = (wid & 3) * 32;

    __nv_bfloat16* sp[2][4];
#pragma unroll
    for (int s = 0; s < 2; s++)
#pragma unroll
        for (int o = 0; o < 4; o++) sp[s][o] = sm + ((s * 4 + o) * 128 * APAD);

    float acc[4][4][4];
#pragma unroll
    for (int i = 0; i < 4; i++)
#pragma unroll
        for (int j = 0; j < 4; j++)
#pragma unroll
            for (int q = 0; q < 4; q++) acc[i][j][q] = 0.f;

    const int nst = Ktot / KC;

    auto issue = [&](int s, int c) {
        int kt = c * KC;
#pragma unroll
        for (int i = 0; i < 2; i++) {
            int u = tid + i * 256;
            int r = u >> 2, kc = (u & 3) * 8;
            size_t ga = (size_t)(bRow + r) * Ktot + kt + kc;
            cp_async16(smem_u32(sp[s][0] + r * APAD + kc), Ah + ga, 16);
            cp_async16(smem_u32(sp[s][1] + r * APAD + kc), Al + ga, 16);
            int ok = (bCol + r) < Ntot ? 16 : 0;
            size_t gb = ok ? ((size_t)(bCol + r) * Ktot + kt + kc) : 0;
            cp_async16(smem_u32(sp[s][2] + r * APAD + kc), Bh + gb, ok);
            cp_async16(smem_u32(sp[s][3] + r * APAD + kc), Bl + gb, ok);
        }
    };

    issue(0, 0);
    CP_COMMIT();

    const int ar = lane & 15, ac = (lane >> 4) * 8;
    for (int c = 0; c < nst; c++) {
        if (c + 1 < nst) { issue((c + 1) & 1, c + 1); CP_COMMIT(); CP_WAIT1(); }
        else CP_WAIT0();
        __syncthreads();
        const __nv_bfloat16* sa_h = sp[c & 1][0];
        const __nv_bfloat16* sa_l = sp[c & 1][1];
        const __nv_bfloat16* sb_h = sp[c & 1][2];
        const __nv_bfloat16* sb_l = sp[c & 1][3];
#pragma unroll
        for (int kk = 0; kk < 2; kk++) {
            int k0 = kk * 16;
            uint32_t bfh[2][4], bfl[2][4];
#pragma unroll
            for (int bt = 0; bt < 2; bt++) {
                ldsm4(bfh[bt], smem_u32(sb_h + (wn + bt * 16 + ar) * APAD + k0 + ac));
                ldsm4(bfl[bt], smem_u32(sb_l + (wn + bt * 16 + ar) * APAD + k0 + ac));
            }
#pragma unroll
            for (int mp = 0; mp < 2; mp++) {
                uint32_t ah2[2][4], al2[2][4];
#pragma unroll
                for (int t = 0; t < 2; t++) {
                    int mt = mp * 2 + t;
                    ldsm4(ah2[t], smem_u32(sa_h + (wm + mt * 16 + ar) * APAD + k0 + ac));
                    ldsm4(al2[t], smem_u32(sa_l + (wm + mt * 16 + ar) * APAD + k0 + ac));
                }
                // term pass 1: Ah*Bh (8 independent accumulators)
#pragma unroll
                for (int t = 0; t < 2; t++)
#pragma unroll
                    for (int nt = 0; nt < 4; nt++) {
                        int bt = nt >> 1, sel = nt & 1;
                        mma16816(acc[mp * 2 + t][nt], ah2[t], bfh[bt][sel], bfh[bt][sel + 2]);
                    }
                // term pass 2: Ah*Bl
#pragma unroll
                for (int t = 0; t < 2; t++)
#pragma unroll
                    for (int nt = 0; nt < 4; nt++) {
                        int bt = nt >> 1, sel = nt & 1;
                        mma16816(acc[mp * 2 + t][nt], ah2[t], bfl[bt][sel], bfl[bt][sel + 2]);
                    }
                // term pass 3: Al*Bh
#pragma unroll
                for (int t = 0; t < 2; t++)
#pragma unroll
                    for (int nt = 0; nt < 4; nt++) {
                        int bt = nt >> 1, sel = nt & 1;
                        mma16816(acc[mp * 2 + t][nt], al2[t], bfh[bt][sel], bfh[bt][sel + 2]);
                    }
            }
        }
        __syncthreads();
    }

    const int g = lane >> 2, t4 = lane & 3;
#pragma unroll
    for (int mt = 0; mt < 4; mt++) {
#pragma unroll
        for (int nt = 0; nt < 4; nt++) {
            int row = bRow + wm + mt * 16 + g;
            int col = bCol + wn + nt * 8 + t4 * 2;
            if (col < Ntot) {
                float* p0 = Cc + (size_t)row * Ntot + col;
                p0[0] = acc[mt][nt][0];
                p0[1] = acc[mt][nt][1];
                float* p1 = p0 + (size_t)8 * Ntot;
                p1[0] = acc[mt][nt][2];
                p1[1] = acc[mt][nt][3];
            }
        }
    }
}

// ---------------- generic NT SGEMM (small batched G = C B^T) --------
__global__ __launch_bounds__(256) void sgemm_nt(const float* __restrict__ A,
                                                const float* __restrict__ B,
                                                float* __restrict__ C,
                                                int M, int N, int K,
                                                long sA, long sB, long sC) {
    A += (size_t)blockIdx.z * sA;
    B += (size_t)blockIdx.z * sB;
    C += (size_t)blockIdx.z * sC;
    __shared__ float As[16][128];
    __shared__ float Bs[16][128];
    int tid = threadIdx.x;
    int bRow = blockIdx.y * 128, bCol = blockIdx.x * 128;
    int tx = tid & 15, ty = tid >> 4;
    float acc[8][8] = {};
    int lr = tid >> 2;
    int lk = (tid & 3) * 4;
    for (int kt = 0; kt < K; kt += 16) {
#pragma unroll
        for (int p = 0; p < 2; p++) {
            int r = lr + p * 64;
            int row = bRow + r;
            float4 v = make_float4(0.f, 0.f, 0.f, 0.f);
            if (row < M) v = *(const float4*)(A + (size_t)row * K + kt + lk);
            As[lk][r] = v.x; As[lk + 1][r] = v.y; As[lk + 2][r] = v.z; As[lk + 3][r] = v.w;
            int col = bCol + r;
            float4 w = make_float4(0.f, 0.f, 0.f, 0.f);
            if (col < N) w = *(const float4*)(B + (size_t)col * K + kt + lk);
            Bs[lk][r] = w.x; Bs[lk + 1][r] = w.y; Bs[lk + 2][r] = w.z; Bs[lk + 3][r] = w.w;
        }
        __syncthreads();
#pragma unroll
        for (int k = 0; k < 16; k++) {
            float ra[8], rb[8];
            *(float4*)ra       = *(const float4*)&As[k][ty * 8];
            *(float4*)(ra + 4) = *(const float4*)&As[k][ty * 8 + 4];
            *(float4*)rb       = *(const float4*)&Bs[k][tx * 8];
            *(float4*)(rb + 4) = *(const float4*)&Bs[k][tx * 8 + 4];
#pragma unroll
            for (int i = 0; i < 8; i++)
#pragma unroll
                for (int j = 0; j < 8; j++)
                    acc[i][j] += ra[i] * rb[j];
        }
        __syncthreads();
    }
    for (int i = 0; i < 8; i++) {
        int row = bRow + ty * 8 + i;
        if (row >= M) continue;
        for (int j = 0; j < 8; j++) {
            int col = bCol + tx * 8 + j;
            if (col < N) C[(size_t)row * N + col] = acc[i][j];
        }
    }
}

// ---------------- depthwise causal conv (k=4) + bias + silu ----------------
__global__ void conv_kernel(const float* __restrict__ cw, const float* __restrict__ cb) {
    size_t idx = (size_t)blockIdx.x * blockDim.x + threadIdx.x;
    if (idx >= (size_t)L * CONVD) return;
    int c = (int)(idx % CONVD);
    int t = (int)(idx / CONVD);
    float acc = cb[c];
#pragma unroll
    for (int k = 0; k < 4; k++) {
        int ts = t - 3 + k;
        if (ts >= 0) acc += cw[c * 4 + k] * g_zx[(size_t)ts * DPROJ + DIN + c];
    }
    g_xc[idx] = acc * sigmoidf_(acc);
}

// ---------------- dt (with direction flip) + softplus ----------------
__global__ void dt_kernel(const float* __restrict__ dt_bias) {
    int idx = blockIdx.x * blockDim.x + threadIdx.x;
    if (idx >= 2 * L * NH) return;
    int h = idx & 31;
    int t = (idx >> 5) & (L - 1);
    int dir = idx >> 17;
    int ts = dir ? (L - 1 - t) : t;
    float v = g_zx[(size_t)ts * DPROJ + DIN + CONVD + dir * NH + h] + dt_bias[h];
    g_dt2[idx] = (v > 20.f) ? v : log1pf(expf(v));
}

// ---------------- B/C split per direction (flip for dir1) ----------------
__global__ void prep_bc_kernel() {
    int idx = blockIdx.x * blockDim.x + threadIdx.x;
    if (idx >= 2 * L * NST) return;
    int n = idx & 127;
    int t = (idx >> 7) & (L - 1);
    int dir = idx >> 19;
    int ts = dir ? (L - 1 - t) : t;
    int off = dir ? 256 : 0;
    const float* p = g_xc + (size_t)ts * CONVD + DIN + off;
    g_Bm[idx] = p[n];
    g_Cm[idx] = p[NST + n];
}

// ---------------- x (flipped) * dt ----------------
__global__ void prep_x_kernel() {
    size_t idx = (size_t)blockIdx.x * blockDim.x + threadIdx.x;
    if (idx >= (size_t)2 * L * DIN) return;
    int d = (int)(idx & 2047);
    int t = (int)((idx >> 11) & (L - 1));
    int dir = (int)(idx >> 23);
    int ts = dir ? (L - 1 - t) : t;
    g_xdt[idx] = g_xc[(size_t)ts * CONVD + d] * g_dt2[((dir << 12) | t) * NH + (d >> 6)];
}

// ---------------- per-chunk cumsum of A*dt ----------------
__global__ void acs_kernel(const float* __restrict__ A_log) {
    int c = blockIdx.x, dir = blockIdx.y, h = threadIdx.x;
    float Ah = -expf(A_log[h]);
    float cum = 0.f;
    float* out = g_Acs + (((dir * NC + c) * NH + h) << 7);
    const float* dtp = g_dt2 + ((size_t)(dir * L + c * CHK)) * NH + h;
    for (int l = 0; l < CHK; l++) {
        cum += Ah * dtp[l * NH];
        out[l] = cum;
    }
}

// ======== tensor-core SSD chunk kernels (bf16 hi/lo split mma.sync) ========
// smem layout (bytes):
#define OFF_ACS 0
#define OFF_MH 1024
#define OFF_ML (OFF_MH + 128 * 136 * 2)
#define OFF_XH (OFF_ML + 128 * 136 * 2)
#define OFF_XL (OFF_XH + 128 * 72 * 2)
#define SSD_SMEM (OFF_XL + 128 * 72 * 2)   // 107520

// ---- ydiag_states_tc: Y_diag = M @ X ; states^T = (B*dec)^T @ X, stored [n][p] ----
__global__ __launch_bounds__(256) void ydiag_states_tc() {
    extern __shared__ __align__(16) char smc[];
    float* sAcs = (float*)(smc + OFF_ACS);
    __nv_bfloat16* Mh = (__nv_bfloat16*)(smc + OFF_MH);
    __nv_bfloat16* Ml = (__nv_bfloat16*)(smc + OFF_ML);
    __nv_bfloat16* Xh = (__nv_bfloat16*)(smc + OFF_XH);
    __nv_bfloat16* Xl = (__nv_bfloat16*)(smc + OFF_XL);
    const int b = blockIdx.x;
    const int h = b & 31, c = (b >> 5) & 31, dir = b >> 10;
    const int tid = threadIdx.x;
    const int wid = tid >> 5, lane = tid & 31;
    const int wy = wid >> 1, wx = wid & 1;
    if (tid < 128) sAcs[tid] = g_Acs[(b << 7) + tid];
    __syncthreads();

    // build M (masked decay * G) and X (xdt) as bf16 hi/lo
    {
        const int l = tid >> 1;
        const int s0 = (tid & 1) * 64;
        const float al = sAcs[l];
        const float* Gp = g_G + ((size_t)(dir * NC + c) << 14) + l * CHK;
#pragma unroll 8
        for (int j = 0; j < 64; j++) {
            int s = s0 + j;
            float m = (l >= s) ? Gp[s] * __expf(al - sAcs[s]) : 0.f;
            split_hilo(m, Mh[l * 136 + s], Ml[l * 136 + s]);
        }
        const float* Xp = g_xdt + ((size_t)(dir * L + c * CHK) + l) * DIN + h * HD;
        int p0 = (tid & 1) * 32;
#pragma unroll 8
        for (int j = 0; j < 32; j++) {
            split_hilo(Xp[p0 + j], Xh[l * 72 + p0 + j], Xl[l * 72 + p0 + j]);
        }
    }
    __syncthreads();

    // lane helpers
    const int ar = lane & 15, ac = (lane >> 4) * 8;                 // A non-trans
    const int grp = lane >> 3;
    const int bkr = (grp & 1) * 8 + (lane & 7), bnc = (grp >> 1) * 8; // B trans
    const int akr = (grp >> 1) * 8 + (lane & 7), amc = (grp & 1) * 8; // A trans
    const int g = lane >> 2, t4 = lane & 3;

    // Y_diag = M(128x128) @ X(128x64); warp tile 32x32
    {
        float acc[2][4][4] = {};
        for (int kk = 0; kk < 8; kk++) {
            int k0 = kk * 16;
            uint32_t bh[2][4], bl[2][4];
#pragma unroll
            for (int ng = 0; ng < 2; ng++) {
                int n0 = wx * 32 + ng * 16;
                ldsm4t(bh[ng], smem_u32(Xh + (k0 + bkr) * 72 + n0 + bnc));
                ldsm4t(bl[ng], smem_u32(Xl + (k0 + bkr) * 72 + n0 + bnc));
            }
            uint32_t ahf[2][4], alf[2][4];
#pragma unroll
            for (int mt = 0; mt < 2; mt++) {
                int m0 = wy * 32 + mt * 16;
                ldsm4(ahf[mt], smem_u32(Mh + (m0 + ar) * 136 + k0 + ac));
                ldsm4(alf[mt], smem_u32(Ml + (m0 + ar) * 136 + k0 + ac));
            }
#pragma unroll
            for (int mt = 0; mt < 2; mt++)
#pragma unroll
                for (int j2 = 0; j2 < 4; j2++) {
                    int ng = j2 >> 1, jj = j2 & 1;
                    mma16816(acc[mt][j2], ahf[mt], bh[ng][jj * 2], bh[ng][jj * 2 + 1]);
                }
#pragma unroll
            for (int mt = 0; mt < 2; mt++)
#pragma unroll
                for (int j2 = 0; j2 < 4; j2++) {
                    int ng = j2 >> 1, jj = j2 & 1;
                    mma16816(acc[mt][j2], ahf[mt], bl[ng][jj * 2], bl[ng][jj * 2 + 1]);
                }
#pragma unroll
            for (int mt = 0; mt < 2; mt++)
#pragma unroll
                for (int j2 = 0; j2 < 4; j2++) {
                    int ng = j2 >> 1, jj = j2 & 1;
                    mma16816(acc[mt][j2], alf[mt], bh[ng][jj * 2], bh[ng][jj * 2 + 1]);
                }
        }
        float* Yp = g_Yd + ((size_t)(dir * L + c * CHK)) * DIN + h * HD;
#pragma unroll
        for (int mt = 0; mt < 2; mt++)
#pragma unroll
            for (int j2 = 0; j2 < 4; j2++) {
                int l1 = wy * 32 + mt * 16 + g;
                int p = wx * 32 + j2 * 8 + t4 * 2;
                Yp[(size_t)l1 * DIN + p]       = acc[mt][j2][0];
                Yp[(size_t)l1 * DIN + p + 1]   = acc[mt][j2][1];
                Yp[(size_t)(l1 + 8) * DIN + p]     = acc[mt][j2][2];
                Yp[(size_t)(l1 + 8) * DIN + p + 1] = acc[mt][j2][3];
            }
    }
    __syncthreads();

    // rebuild M buffers with B*dec
    {
        const int l = tid >> 1;
        const int n0 = (tid & 1) * 64;
        const float dec = __expf(sAcs[127] - sAcs[l]);
        const float* Bp = g_Bm + ((size_t)(dir * L + c * CHK) + l) * NST;
#pragma unroll 8
        for (int j = 0; j < 64; j++) {
            split_hilo(Bp[n0 + j] * dec, Mh[l * 136 + n0 + j], Ml[l * 136 + n0 + j]);
        }
    }
    __syncthreads();

    // states[n][p] = sum_l Bdec[l][n] * X[l][p];  A via trans ldmatrix (m=n, k=l)
    {
        float acc[2][4][4] = {};
        for (int kk = 0; kk < 8; kk++) {
            int k0 = kk * 16;
            uint32_t bh[2][4], bl[2][4];
#pragma unroll
            for (int ng = 0; ng < 2; ng++) {
                int n0 = wx * 32 + ng * 16;
                ldsm4t(bh[ng], smem_u32(Xh + (k0 + bkr) * 72 + n0 + bnc));
                ldsm4t(bl[ng], smem_u32(Xl + (k0 + bkr) * 72 + n0 + bnc));
            }
            uint32_t ahf[2][4], alf[2][4];
#pragma unroll
            for (int mt = 0; mt < 2; mt++) {
                int m0 = wy * 32 + mt * 16;
                ldsm4t(ahf[mt], smem_u32(Mh + (k0 + akr) * 136 + m0 + amc));
                ldsm4t(alf[mt], smem_u32(Ml + (k0 + akr) * 136 + m0 + amc));
            }
#pragma unroll
            for (int mt = 0; mt < 2; mt++)
#pragma unroll
                for (int j2 = 0; j2 < 4; j2++) {
                    int ng = j2 >> 1, jj = j2 & 1;
                    mma16816(acc[mt][j2], ahf[mt], bh[ng][jj * 2], bh[ng][jj * 2 + 1]);
                }
#pragma unroll
            for (int mt = 0; mt < 2; mt++)
#pragma unroll
                for (int j2 = 0; j2 < 4; j2++) {
                    int ng = j2 >> 1, jj = j2 & 1;
                    mma16816(acc[mt][j2], ahf[mt], bl[ng][jj * 2], bl[ng][jj * 2 + 1]);
                }
#pragma unroll
            for (int mt = 0; mt < 2; mt++)
#pragma unroll
                for (int j2 = 0; j2 < 4; j2++) {
                    int ng = j2 >> 1, jj = j2 & 1;
                    mma16816(acc[mt][j2], alf[mt], bh[ng][jj * 2], bh[ng][jj * 2 + 1]);
                }
        }
        float* Sp = g_states + ((size_t)b << 13);
#pragma unroll
        for (int mt = 0; mt < 2; mt++)
#pragma unroll
            for (int j2 = 0; j2 < 4; j2++) {
                int n1 = wy * 32 + mt * 16 + g;
                int p = wx * 32 + j2 * 8 + t4 * 2;
                Sp[(size_t)n1 * HD + p]       = acc[mt][j2][0];
                Sp[(size_t)n1 * HD + p + 1]   = acc[mt][j2][1];
                Sp[(size_t)(n1 + 8) * HD + p]     = acc[mt][j2][2];
                Sp[(size_t)(n1 + 8) * HD + p + 1] = acc[mt][j2][3];
            }
    }
}

// ---------------- inter-chunk recurrence (layout-agnostic elementwise) ----------------
__global__ void recur_kernel() {
    int b = blockIdx.x;
    int dir = b >> 5, h = b & 31;
    int tid = threadIdx.x;
    float Hreg[32];
#pragma unroll
    for (int k = 0; k < 32; k++) Hreg[k] = 0.f;
    for (int c = 0; c < NC; c++) {
        int sb = (dir * NC + c) * NH + h;
        float dec = expf(g_Acs[(sb << 7) + 127]);
        size_t base = ((size_t)sb << 13);
#pragma unroll
        for (int k = 0; k < 32; k++) {
            size_t off = base + tid + k * 256;
            float s = g_states[off];
            g_states[off] = Hreg[k];
            Hreg[k] = dec * Hreg[k] + s;
        }
    }
}

// ---- yoff_tc: Yd += (C*exp(Acs)) @ states[n][p] + x*D ----
__global__ __launch_bounds__(256) void yoff_tc(const float* __restrict__ Dv) {
    extern __shared__ __align__(16) char smc[];
    float* sAcs = (float*)(smc + OFF_ACS);
    __nv_bfloat16* Mh = (__nv_bfloat16*)(smc + OFF_MH);
    __nv_bfloat16* Ml = (__nv_bfloat16*)(smc + OFF_ML);
    __nv_bfloat16* Xh = (__nv_bfloat16*)(smc + OFF_XH);
    __nv_bfloat16* Xl = (__nv_bfloat16*)(smc + OFF_XL);
    const int b = blockIdx.x;
    const int h = b & 31, c = (b >> 5) & 31, dir = b >> 10;
    const int tid = threadIdx.x;
    const int wid = tid >> 5, lane = tid & 31;
    const int wy = wid >> 1, wx = wid & 1;
    if (tid < 128) sAcs[tid] = g_Acs[(b << 7) + tid];
    __syncthreads();

    // build A = C[l][n]*exp(Acs[l]) and B-src = states[n][p]
    {
        const int l = tid >> 1;
        const int n0 = (tid & 1) * 64;
        const float e = __expf(sAcs[l]);
        const float* Cp = g_Cm + ((size_t)(dir * L + c * CHK) + l) * NST;
#pragma unroll 8
        for (int j = 0; j < 64; j++) {
            split_hilo(Cp[n0 + j] * e, Mh[l * 136 + n0 + j], Ml[l * 136 + n0 + j]);
        }
        const float* Sp = g_states + ((size_t)b << 13) + (size_t)l * HD;
        int p0 = (tid & 1) * 32;
#pragma unroll 8
        for (int j = 0; j < 32; j++) {
            split_hilo(Sp[p0 + j], Xh[l * 72 + p0 + j], Xl[l * 72 + p0 + j]);
        }
    }
    __syncthreads();

    const int ar = lane & 15, ac = (lane >> 4) * 8;
    const int grp = lane >> 3;
    const int bkr = (grp & 1) * 8 + (lane & 7), bnc = (grp >> 1) * 8;
    const int g = lane >> 2, t4 = lane & 3;

    float acc[2][4][4] = {};
    for (int kk = 0; kk < 8; kk++) {
        int k0 = kk * 16;
        uint32_t bh[2][4], bl[2][4];
#pragma unroll
        for (int ng = 0; ng < 2; ng++) {
            int n0 = wx * 32 + ng * 16;
            ldsm4t(bh[ng], smem_u32(Xh + (k0 + bkr) * 72 + n0 + bnc));
            ldsm4t(bl[ng], smem_u32(Xl + (k0 + bkr) * 72 + n0 + bnc));
        }
        uint32_t ahf[2][4], alf[2][4];
#pragma unroll
        for (int mt = 0; mt < 2; mt++) {
            int m0 = wy * 32 + mt * 16;
            ldsm4(ahf[mt], smem_u32(Mh + (m0 + ar) * 136 + k0 + ac));
            ldsm4(alf[mt], smem_u32(Ml + (m0 + ar) * 136 + k0 + ac));
        }
#pragma unroll
        for (int mt = 0; mt < 2; mt++)
#pragma unroll
            for (int j2 = 0; j2 < 4; j2++) {
                int ng = j2 >> 1, jj = j2 & 1;
                mma16816(acc[mt][j2], ahf[mt], bh[ng][jj * 2], bh[ng][jj * 2 + 1]);
            }
#pragma unroll
        for (int mt = 0; mt < 2; mt++)
#pragma unroll
            for (int j2 = 0; j2 < 4; j2++) {
                int ng = j2 >> 1, jj = j2 & 1;
                mma16816(acc[mt][j2], ahf[mt], bl[ng][jj * 2], bl[ng][jj * 2 + 1]);
            }
#pragma unroll
        for (int mt = 0; mt < 2; mt++)
#pragma unroll
            for (int j2 = 0; j2 < 4; j2++) {
                int ng = j2 >> 1, jj = j2 & 1;
                mma16816(acc[mt][j2], alf[mt], bh[ng][jj * 2], bh[ng][jj * 2 + 1]);
            }
    }

    const float Dh = Dv[h];
    float* Yp = g_Yd + ((size_t)(dir * L + c * CHK)) * DIN + h * HD;
#pragma unroll
    for (int mt = 0; mt < 2; mt++)
#pragma unroll
        for (int j2 = 0; j2 < 4; j2++) {
            int l1 = wy * 32 + mt * 16 + g;
            int p = wx * 32 + j2 * 8 + t4 * 2;
#pragma unroll
            for (int rr = 0; rr < 2; rr++) {
                int l = l1 + rr * 8;
                int tglob = c * CHK + l;
                int ts = dir ? (L - 1 - tglob) : tglob;
                const float* xr = g_xc + (size_t)ts * CONVD + h * HD;
                size_t o = (size_t)l * DIN + p;
                Yp[o]     += acc[mt][j2][rr * 2]     + xr[p] * Dh;
                Yp[o + 1] += acc[mt][j2][rr * 2 + 1] + xr[p + 1] * Dh;
            }
        }
}

// ---------------- fd[t,h] = x_og[t] . fc_D_w[h] + D[h] ----------------
__global__ void fcD_kernel(const float* __restrict__ W, const float* __restrict__ Dv) {
    int t = blockIdx.x;
    __shared__ float sx[DIN];
    int tid = threadIdx.x;
#pragma unroll
    for (int k = 0; k < 8; k++) sx[tid + k * 256] = g_xc[(size_t)t * CONVD + tid + k * 256];
    __syncthreads();
    int warp = tid >> 5, lane = tid & 31;
    for (int q = 0; q < 4; q++) {
        int h = warp * 4 + q;
        const float* wr = W + (size_t)h * DIN;
        float acc = 0.f;
        for (int i = 0; i < 64; i++) {
            int d = i * 32 + lane;
            acc += sx[d] * wr[d];
        }
        for (int o = 16; o > 0; o >>= 1) acc += __shfl_down_sync(0xffffffffu, acc, o);
        if (lane == 0) g_fd[t * NH + h] = acc + Dv[h];
    }
}

// ---------------- shift + merge dirs + skip + gate + RMSNorm -> bf16 hi/lo ----------------
__global__ void combine_kernel(const float* __restrict__ norm_w) {
    int t = blockIdx.x;
    int tid = threadIdx.x;
    __shared__ float red[256];
    __shared__ float sc;
    float yg[8];
    float ss = 0.f;
#pragma unroll
    for (int k = 0; k < 8; k++) {
        int d = tid + k * 256;
        float yfw = (t > 0) ? g_Yd[((size_t)(t - 1)) * DIN + d] : 0.f;
        float ybw = (t < L - 1) ? g_Yd[((size_t)(L + (L - 2 - t))) * DIN + d] : 0.f;
        float x = g_xc[(size_t)t * CONVD + d];
        float fdv = g_fd[t * NH + (d >> 6)];
        float z = g_zx[(size_t)t * DPROJ + d];
        float v = (yfw + ybw + x * fdv) * (z * sigmoidf_(z));
        yg[k] = v;
        ss += v * v;
    }
    red[tid] = ss;
    __syncthreads();
    for (int o = 128; o > 0; o >>= 1) {
        if (tid < o) red[tid] += red[tid + o];
        __syncthreads();
    }
    if (tid == 0) sc = rsqrtf(red[0] * (1.f / DIN) + EPSV);
    __syncthreads();
    float s = sc;
#pragma unroll
    for (int k = 0; k < 8; k++) {
        int d = tid + k * 256;
        float v = yg[k] * s * norm_w[d];
        split_hilo(v, g_ynh[(size_t)t * DIN + d], g_ynl[(size_t)t * DIN + d]);
    }
}

extern "C" void kernel_launch(void* const* d_in, const int* in_sizes, int n_in,
                              void* d_out, int out_size) {
    const float* u          = (const float*)d_in[0];
    const float* in_proj_w  = (const float*)d_in[1];
    const float* conv_w     = (const float*)d_in[2];
    const float* conv_b     = (const float*)d_in[3];
    const float* dt_bias    = (const float*)d_in[4];
    const float* A_log      = (const float*)d_in[5];
    const float* Dv         = (const float*)d_in[6];
    const float* fc_D_w     = (const float*)d_in[7];
    const float* norm_w     = (const float*)d_in[8];
    const float* out_proj_w = (const float*)d_in[9];
    float* out = (float*)d_out;

    float *zx, *Bm, *Cm, *G;
    __nv_bfloat16 *uh, *ul, *wih, *wil, *ynh, *ynl, *woh, *wol;
    cudaGetSymbolAddress((void**)&zx, g_zx);
    cudaGetSymbolAddress((void**)&Bm, g_Bm);
    cudaGetSymbolAddress((void**)&Cm, g_Cm);
    cudaGetSymbolAddress((void**)&G, g_G);
    cudaGetSymbolAddress((void**)&uh, g_uh);
    cudaGetSymbolAddress((void**)&ul, g_ul);
    cudaGetSymbolAddress((void**)&wih, g_wih);
    cudaGetSymbolAddress((void**)&wil, g_wil);
    cudaGetSymbolAddress((void**)&ynh, g_ynh);
    cudaGetSymbolAddress((void**)&ynl, g_ynl);
    cudaGetSymbolAddress((void**)&woh, g_woh);
    cudaGetSymbolAddress((void**)&wol, g_wol);

    const int smemB = 2 * 4 * 128 * APAD * 2;  // 81920 B
    cudaFuncSetAttribute(gemm_mma, cudaFuncAttributeMaxDynamicSharedMemorySize, smemB);
    cudaFuncSetAttribute(ydiag_states_tc, cudaFuncAttributeMaxDynamicSharedMemorySize, SSD_SMEM);
    cudaFuncSetAttribute(yoff_tc, cudaFuncAttributeMaxDynamicSharedMemorySize, SSD_SMEM);

    // 0) split inputs/weights into bf16 hi/lo
    cvt_hilo_kernel<<<((size_t)L * DM + 255) / 256, 256>>>(u, uh, ul, (size_t)L * DM);
    cvt_hilo_kernel<<<((size_t)DPROJ * DM + 255) / 256, 256>>>(in_proj_w, wih, wil, (size_t)DPROJ * DM);
    cvt_hilo_kernel<<<((size_t)DM * DIN + 255) / 256, 256>>>(out_proj_w, woh, wol, (size_t)DM * DIN);

    // 1) in_proj
    gemm_mma<<<dim3((DPROJ + 127) / 128, L / 128), 256, smemB>>>(uh, ul, wih, wil, zx, DPROJ, DM);
    // 2) conv + silu
    conv_kernel<<<((size_t)L * CONVD + 255) / 256, 256>>>(conv_w, conv_b);
    // 3) dt softplus
    dt_kernel<<<(2 * L * NH + 255) / 256, 256>>>(dt_bias);
    // 4) B/C and x*dt prep
    prep_bc_kernel<<<(2 * L * NST + 255) / 256, 256>>>();
    prep_x_kernel<<<((size_t)2 * L * DIN + 255) / 256, 256>>>();
    // 5) per-chunk cumsum of A*dt
    acs_kernel<<<dim3(NC, 2), 32>>>(A_log);
    // 6) G = C B^T per (dir,chunk)
    sgemm_nt<<<dim3(1, 1, 2 * NC), 256>>>(Cm, Bm, G, CHK, CHK, NST,
                                          CHK * NST, CHK * NST, CHK * CHK);
    // 7) Y_diag + chunk states (tensor cores)
    ydiag_states_tc<<<2 * NC * NH, 256, SSD_SMEM>>>();
    // 8) inter-chunk recurrence
    recur_kernel<<<2 * NH, 256>>>();
    // 9) Y_off + x*D (tensor cores)
    yoff_tc<<<2 * NC * NH, 256, SSD_SMEM>>>(Dv);
    // 10) fd
    fcD_kernel<<<L, 256>>>(fc_D_w, Dv);
    // 11) shift/merge/gate/RMSNorm
    combine_kernel<<<L, 256>>>(norm_w);
    // 12) out_proj
    gemm_mma<<<dim3(DM / 128, L / 128), 256, smemB>>>(ynh, ynl, woh, wol, out, DM, DIN);
}

// round 6
// speedup vs baseline: 1.2397x; 1.2397x over previous
#include <cuda_runtime.h>
#include <cuda_bf16.h>
#include <cuda_fp16.h>
#include <math.h>
#include <stdint.h>

#define L 4096
#define DM 1024
#define DIN 2048
#define NH 32
#define HD 64
#define NST 128
#define CONVD 2560
#define DPROJ 4672
#define CHK 128
#define NC 32
#define EPSV 1e-5f

// ---------------- scratch (static device globals; no allocation) ----------------
__device__ float g_zx[(size_t)L * DPROJ];        // in_proj output (4096 x 4672)
__device__ float g_xc[(size_t)L * CONVD];        // conv+silu output (x_og | BC)
__device__ float g_dt2[2 * L * NH];              // softplus dt, both dirs
__device__ float g_Bm[(size_t)2 * L * NST];      // B per dir (flipped for dir1)
__device__ float g_Cm[(size_t)2 * L * NST];      // C per dir
__device__ float g_xdt[(size_t)2 * L * DIN];     // x (flipped) * dt
__device__ float g_Acs[2 * NC * NH * CHK];       // per-chunk cumsum of A*dt
__device__ float g_G[(size_t)2 * NC * CHK * CHK];// C B^T per (dir,chunk)
__device__ float g_Yd[(size_t)2 * L * DIN];      // Y (diag then += off + x*D)
__device__ float g_states[(size_t)2 * NC * NH * HD * NST];
__device__ float g_fd[L * NH];

// fp16 buffers for tensor-core GEMMs (A split hi/lo, weights single fp16)
__device__ __align__(16) __half g_uh[(size_t)L * DM];
__device__ __align__(16) __half g_ul[(size_t)L * DM];
__device__ __align__(16) __half g_wi[(size_t)DPROJ * DM];
__device__ __align__(16) __half g_ynh[(size_t)L * DIN];
__device__ __align__(16) __half g_ynl[(size_t)L * DIN];
__device__ __align__(16) __half g_wo[(size_t)DM * DIN];

__device__ __forceinline__ float sigmoidf_(float x) { return 1.f / (1.f + expf(-x)); }

__device__ __forceinline__ uint32_t smem_u32(const void* p) {
    uint32_t a;
    asm("{ .reg .u64 tmp; cvta.to.shared.u64 tmp, %1; cvt.u32.u64 %0, tmp; }" : "=r"(a) : "l"(p));
    return a;
}
__device__ __forceinline__ void cp_async16(uint32_t dst, const void* src, int srcsize) {
    asm volatile("cp.async.cg.shared.global [%0], [%1], 16, %2;"
                 :: "r"(dst), "l"(src), "r"(srcsize));
}
#define CP_COMMIT() asm volatile("cp.async.commit_group;" ::: "memory")
#define CP_WAIT1()  asm volatile("cp.async.wait_group 1;"  ::: "memory")
#define CP_WAIT0()  asm volatile("cp.async.wait_group 0;"  ::: "memory")

__device__ __forceinline__ void ldsm4(uint32_t* r, uint32_t addr) {
    asm volatile("ldmatrix.sync.aligned.m8n8.x4.shared.b16 {%0,%1,%2,%3}, [%4];"
                 : "=r"(r[0]), "=r"(r[1]), "=r"(r[2]), "=r"(r[3]) : "r"(addr));
}
__device__ __forceinline__ void mma16816h(float* c, const uint32_t* a, uint32_t b0, uint32_t b1) {
    asm volatile("mma.sync.aligned.m16n8k16.row.col.f32.f16.f16.f32 "
                 "{%0,%1,%2,%3}, {%4,%5,%6,%7}, {%8,%9}, {%0,%1,%2,%3};"
                 : "+f"(c[0]), "+f"(c[1]), "+f"(c[2]), "+f"(c[3])
                 : "r"(a[0]), "r"(a[1]), "r"(a[2]), "r"(a[3]), "r"(b0), "r"(b1));
}
__device__ __forceinline__ void split_hilo_h(float v, __half& h, __half& l) {
    h = __float2half(v);
    l = __float2half(v - __half2float(h));
}

// ---------------- fp32 -> fp16 hi/lo split (activations) ----------------
__global__ void cvt_hilo_kernel(const float* __restrict__ x,
                                __half* __restrict__ hi,
                                __half* __restrict__ lo, size_t n) {
    size_t i = (size_t)blockIdx.x * blockDim.x + threadIdx.x;
    if (i >= n) return;
    __half h, lv;
    split_hilo_h(x[i], h, lv);
    hi[i] = h; lo[i] = lv;
}
// ---------------- fp32 -> single fp16 (weights) ----------------
__global__ void cvt_h_kernel(const float* __restrict__ x, __half* __restrict__ o, size_t n) {
    size_t i = (size_t)blockIdx.x * blockDim.x + threadIdx.x;
    if (i >= n) return;
    o[i] = __float2half(x[i]);
}

// ===== mma.sync fp16 2-term GEMM: C[m,n] = sum_k (Ah+Al)[m,k]*B[n,k] =====
// CTA 128x128 tile, 8 warps (2x4), warp 64x32. K-chunk 32, cp.async double buffer.
#define KC 32
#define APAD 40   // smem row stride in halfs (80B, ldmatrix conflict-free)

__global__ __launch_bounds__(256, 2) void gemm_2t(
    const __half* __restrict__ Ah, const __half* __restrict__ Al,
    const __half* __restrict__ Bw,
    float* __restrict__ Cc, int Ntot, int Ktot) {
    extern __shared__ __align__(16) __half sm[];
    const int tid = threadIdx.x;
    const int bRow = blockIdx.y * 128, bCol = blockIdx.x * 128;
    const int wid = tid >> 5, lane = tid & 31;
    const int wm = (wid >> 2) * 64, wn = (wid & 3) * 32;

    // stage layout: [stage][op 0=Ah 1=Al 2=B][128][APAD]
    __half* sp[2][3];
#pragma unroll
    for (int s = 0; s < 2; s++)
#pragma unroll
        for (int o = 0; o < 3; o++) sp[s][o] = sm + ((s * 3 + o) * 128 * APAD);

    float acc[4][4][4];
#pragma unroll
    for (int i = 0; i < 4; i++)
#pragma unroll
        for (int j = 0; j < 4; j++)
#pragma unroll
            for (int q = 0; q < 4; q++) acc[i][j][q] = 0.f;

    const int nst = Ktot / KC;

    auto issue = [&](int s, int c) {
        int kt = c * KC;
#pragma unroll
        for (int i = 0; i < 2; i++) {
            int u = tid + i * 256;          // 0..511 16B units
            int r = u >> 2, kc = (u & 3) * 8;
            size_t ga = (size_t)(bRow + r) * Ktot + kt + kc;
            cp_async16(smem_u32(sp[s][0] + r * APAD + kc), Ah + ga, 16);
            cp_async16(smem_u32(sp[s][1] + r * APAD + kc), Al + ga, 16);
            int ok = (bCol + r) < Ntot ? 16 : 0;
            size_t gb = ok ? ((size_t)(bCol + r) * Ktot + kt + kc) : 0;
            cp_async16(smem_u32(sp[s][2] + r * APAD + kc), Bw + gb, ok);
        }
    };

    issue(0, 0);
    CP_COMMIT();

    const int ar = lane & 15, ac = (lane >> 4) * 8;
    for (int c = 0; c < nst; c++) {
        if (c + 1 < nst) { issue((c + 1) & 1, c + 1); CP_COMMIT(); CP_WAIT1(); }
        else CP_WAIT0();
        __syncthreads();
        const __half* sa_h = sp[c & 1][0];
        const __half* sa_l = sp[c & 1][1];
        const __half* sb   = sp[c & 1][2];
#pragma unroll
        for (int kk = 0; kk < 2; kk++) {
            int k0 = kk * 16;
            uint32_t bf[2][4];
#pragma unroll
            for (int bt = 0; bt < 2; bt++)
                ldsm4(bf[bt], smem_u32(sb + (wn + bt * 16 + ar) * APAD + k0 + ac));
#pragma unroll
            for (int mt = 0; mt < 4; mt++) {
                uint32_t afh[4], afl[4];
                ldsm4(afh, smem_u32(sa_h + (wm + mt * 16 + ar) * APAD + k0 + ac));
                ldsm4(afl, smem_u32(sa_l + (wm + mt * 16 + ar) * APAD + k0 + ac));
#pragma unroll
                for (int nt = 0; nt < 4; nt++) {
                    int bt = nt >> 1, sel = nt & 1;
                    mma16816h(acc[mt][nt], afh, bf[bt][sel], bf[bt][sel + 2]);
                }
#pragma unroll
                for (int nt = 0; nt < 4; nt++) {
                    int bt = nt >> 1, sel = nt & 1;
                    mma16816h(acc[mt][nt], afl, bf[bt][sel], bf[bt][sel + 2]);
                }
            }
        }
        __syncthreads();
    }

    const int g = lane >> 2, t4 = lane & 3;
#pragma unroll
    for (int mt = 0; mt < 4; mt++) {
#pragma unroll
        for (int nt = 0; nt < 4; nt++) {
            int row = bRow + wm + mt * 16 + g;
            int col = bCol + wn + nt * 8 + t4 * 2;
            if (col < Ntot) {
                float* p0 = Cc + (size_t)row * Ntot + col;
                p0[0] = acc[mt][nt][0];
                p0[1] = acc[mt][nt][1];
                float* p1 = p0 + (size_t)8 * Ntot;
                p1[0] = acc[mt][nt][2];
                p1[1] = acc[mt][nt][3];
            }
        }
    }
}

// ---------------- generic NT SGEMM (small batched G = C B^T) --------
__global__ __launch_bounds__(256) void sgemm_nt(const float* __restrict__ A,
                                                const float* __restrict__ B,
                                                float* __restrict__ C,
                                                int M, int N, int K,
                                                long sA, long sB, long sC) {
    A += (size_t)blockIdx.z * sA;
    B += (size_t)blockIdx.z * sB;
    C += (size_t)blockIdx.z * sC;
    __shared__ float As[16][128];
    __shared__ float Bs[16][128];
    int tid = threadIdx.x;
    int bRow = blockIdx.y * 128, bCol = blockIdx.x * 128;
    int tx = tid & 15, ty = tid >> 4;
    float acc[8][8] = {};
    int lr = tid >> 2;
    int lk = (tid & 3) * 4;
    for (int kt = 0; kt < K; kt += 16) {
#pragma unroll
        for (int p = 0; p < 2; p++) {
            int r = lr + p * 64;
            int row = bRow + r;
            float4 v = make_float4(0.f, 0.f, 0.f, 0.f);
            if (row < M) v = *(const float4*)(A + (size_t)row * K + kt + lk);
            As[lk][r] = v.x; As[lk + 1][r] = v.y; As[lk + 2][r] = v.z; As[lk + 3][r] = v.w;
            int col = bCol + r;
            float4 w = make_float4(0.f, 0.f, 0.f, 0.f);
            if (col < N) w = *(const float4*)(B + (size_t)col * K + kt + lk);
            Bs[lk][r] = w.x; Bs[lk + 1][r] = w.y; Bs[lk + 2][r] = w.z; Bs[lk + 3][r] = w.w;
        }
        __syncthreads();
#pragma unroll
        for (int k = 0; k < 16; k++) {
            float ra[8], rb[8];
            *(float4*)ra       = *(const float4*)&As[k][ty * 8];
            *(float4*)(ra + 4) = *(const float4*)&As[k][ty * 8 + 4];
            *(float4*)rb       = *(const float4*)&Bs[k][tx * 8];
            *(float4*)(rb + 4) = *(const float4*)&Bs[k][tx * 8 + 4];
#pragma unroll
            for (int i = 0; i < 8; i++)
#pragma unroll
                for (int j = 0; j < 8; j++)
                    acc[i][j] += ra[i] * rb[j];
        }
        __syncthreads();
    }
    for (int i = 0; i < 8; i++) {
        int row = bRow + ty * 8 + i;
        if (row >= M) continue;
        for (int j = 0; j < 8; j++) {
            int col = bCol + tx * 8 + j;
            if (col < N) C[(size_t)row * N + col] = acc[i][j];
        }
    }
}

// ---------------- depthwise causal conv (k=4) + bias + silu ----------------
__global__ void conv_kernel(const float* __restrict__ cw, const float* __restrict__ cb) {
    size_t idx = (size_t)blockIdx.x * blockDim.x + threadIdx.x;
    if (idx >= (size_t)L * CONVD) return;
    int c = (int)(idx % CONVD);
    int t = (int)(idx / CONVD);
    float acc = cb[c];
#pragma unroll
    for (int k = 0; k < 4; k++) {
        int ts = t - 3 + k;
        if (ts >= 0) acc += cw[c * 4 + k] * g_zx[(size_t)ts * DPROJ + DIN + c];
    }
    g_xc[idx] = acc * sigmoidf_(acc);
}

// ---------------- dt (with direction flip) + softplus ----------------
__global__ void dt_kernel(const float* __restrict__ dt_bias) {
    int idx = blockIdx.x * blockDim.x + threadIdx.x;
    if (idx >= 2 * L * NH) return;
    int h = idx & 31;
    int t = (idx >> 5) & (L - 1);
    int dir = idx >> 17;
    int ts = dir ? (L - 1 - t) : t;
    float v = g_zx[(size_t)ts * DPROJ + DIN + CONVD + dir * NH + h] + dt_bias[h];
    g_dt2[idx] = (v > 20.f) ? v : log1pf(expf(v));
}

// ---------------- B/C split per direction (flip for dir1) ----------------
__global__ void prep_bc_kernel() {
    int idx = blockIdx.x * blockDim.x + threadIdx.x;
    if (idx >= 2 * L * NST) return;
    int n = idx & 127;
    int t = (idx >> 7) & (L - 1);
    int dir = idx >> 19;
    int ts = dir ? (L - 1 - t) : t;
    int off = dir ? 256 : 0;
    const float* p = g_xc + (size_t)ts * CONVD + DIN + off;
    g_Bm[idx] = p[n];
    g_Cm[idx] = p[NST + n];
}

// ---------------- x (flipped) * dt ----------------
__global__ void prep_x_kernel() {
    size_t idx = (size_t)blockIdx.x * blockDim.x + threadIdx.x;
    if (idx >= (size_t)2 * L * DIN) return;
    int d = (int)(idx & 2047);
    int t = (int)((idx >> 11) & (L - 1));
    int dir = (int)(idx >> 23);
    int ts = dir ? (L - 1 - t) : t;
    g_xdt[idx] = g_xc[(size_t)ts * CONVD + d] * g_dt2[((dir << 12) | t) * NH + (d >> 6)];
}

// ---------------- per-chunk cumsum of A*dt ----------------
__global__ void acs_kernel(const float* __restrict__ A_log) {
    int c = blockIdx.x, dir = blockIdx.y, h = threadIdx.x;
    float Ah = -expf(A_log[h]);
    float cum = 0.f;
    float* out = g_Acs + (((dir * NC + c) * NH + h) << 7);
    const float* dtp = g_dt2 + ((size_t)(dir * L + c * CHK)) * NH + h;
    for (int l = 0; l < CHK; l++) {
        cum += Ah * dtp[l * NH];
        out[l] = cum;
    }
}

// ---------------- per (dir,chunk,head): Y_diag = (G.*Lmat)@xdt ; states = B^T @ (decay.*xdt) ----
__global__ __launch_bounds__(256) void ydiag_states_kernel() {
    int b = blockIdx.x;
    int h = b & 31, c = (b >> 5) & 31, dir = b >> 10;
    int tid = threadIdx.x;
    __shared__ float sAcs[CHK];
    __shared__ float sMl[CHK][17];
    __shared__ float sXs[16][68];
    __shared__ float sB[16][132];
    __shared__ float sXd[16][68];
    if (tid < CHK) sAcs[tid] = g_Acs[(b << 7) + tid];
    __syncthreads();
    const float* Gp = g_G + ((size_t)(dir * NC + c) << 14);
    const float* Xp = g_xdt + ((size_t)(dir * L + c * CHK)) * DIN + h * HD;
    int tx = tid & 15, ty = tid >> 4;
    float acc[8][4] = {};
    int l0 = tid >> 1, skb = (tid & 1) * 8;
    for (int st = 0; st < 8; st++) {
#pragma unroll
        for (int i = 0; i < 8; i++) {
            int s = st * 16 + skb + i;
            float g = Gp[l0 * CHK + s];
            sMl[l0][skb + i] = (l0 >= s) ? g * expf(sAcs[l0] - sAcs[s]) : 0.f;
        }
        {
            int sk = tid >> 4, p0 = (tid & 15) * 4;
            float4 v = *(const float4*)(Xp + (size_t)(st * 16 + sk) * DIN + p0);
            sXs[sk][p0] = v.x; sXs[sk][p0 + 1] = v.y; sXs[sk][p0 + 2] = v.z; sXs[sk][p0 + 3] = v.w;
        }
        __syncthreads();
#pragma unroll
        for (int sk = 0; sk < 16; sk++) {
            float xb0 = sXs[sk][tx * 4], xb1 = sXs[sk][tx * 4 + 1];
            float xb2 = sXs[sk][tx * 4 + 2], xb3 = sXs[sk][tx * 4 + 3];
#pragma unroll
            for (int i = 0; i < 8; i++) {
                float m = sMl[ty * 8 + i][sk];
                acc[i][0] += m * xb0; acc[i][1] += m * xb1;
                acc[i][2] += m * xb2; acc[i][3] += m * xb3;
            }
        }
        __syncthreads();
    }
    float* Yp = g_Yd + ((size_t)(dir * L + c * CHK)) * DIN + h * HD;
#pragma unroll
    for (int i = 0; i < 8; i++)
#pragma unroll
        for (int j = 0; j < 4; j++)
            Yp[(size_t)(ty * 8 + i) * DIN + tx * 4 + j] = acc[i][j];

    // ---- states ----
    float accS[8][4] = {};
    int n0 = (tid & 31) * 4;
    int p0s = (tid >> 5) * 8;
    float lastA = sAcs[127];
    const float* Bp = g_Bm + ((size_t)(dir * L + c * CHK)) * NST;
    for (int lt = 0; lt < 8; lt++) {
        {
            int lk = tid >> 4, nb = (tid & 15) * 8;
            float4 v0 = *(const float4*)(Bp + (size_t)(lt * 16 + lk) * NST + nb);
            float4 v1 = *(const float4*)(Bp + (size_t)(lt * 16 + lk) * NST + nb + 4);
            sB[lk][nb] = v0.x; sB[lk][nb + 1] = v0.y; sB[lk][nb + 2] = v0.z; sB[lk][nb + 3] = v0.w;
            sB[lk][nb + 4] = v1.x; sB[lk][nb + 5] = v1.y; sB[lk][nb + 6] = v1.z; sB[lk][nb + 7] = v1.w;
            int pb = (tid & 15) * 4;
            float dec = expf(lastA - sAcs[lt * 16 + lk]);
            float4 xv = *(const float4*)(Xp + (size_t)(lt * 16 + lk) * DIN + pb);
            sXd[lk][pb] = xv.x * dec; sXd[lk][pb + 1] = xv.y * dec;
            sXd[lk][pb + 2] = xv.z * dec; sXd[lk][pb + 3] = xv.w * dec;
        }
        __syncthreads();
#pragma unroll
        for (int lk2 = 0; lk2 < 16; lk2++) {
            float pv[8];
#pragma unroll
            for (int i = 0; i < 8; i++) pv[i] = sXd[lk2][p0s + i];
            float nv0 = sB[lk2][n0], nv1 = sB[lk2][n0 + 1];
            float nv2 = sB[lk2][n0 + 2], nv3 = sB[lk2][n0 + 3];
#pragma unroll
            for (int i = 0; i < 8; i++) {
                accS[i][0] += pv[i] * nv0; accS[i][1] += pv[i] * nv1;
                accS[i][2] += pv[i] * nv2; accS[i][3] += pv[i] * nv3;
            }
        }
        __syncthreads();
    }
    float* Sp = g_states + ((size_t)b << 13);
#pragma unroll
    for (int i = 0; i < 8; i++)
#pragma unroll
        for (int j = 0; j < 4; j++)
            Sp[(size_t)(p0s + i) * NST + n0 + j] = accS[i][j];
}

// ---------------- inter-chunk recurrence ----------------
__global__ void recur_kernel() {
    int b = blockIdx.x;
    int dir = b >> 5, h = b & 31;
    int tid = threadIdx.x;
    float Hreg[32];
#pragma unroll
    for (int k = 0; k < 32; k++) Hreg[k] = 0.f;
    for (int c = 0; c < NC; c++) {
        int sb = (dir * NC + c) * NH + h;
        float dec = expf(g_Acs[(sb << 7) + 127]);
        size_t base = ((size_t)sb << 13);
#pragma unroll
        for (int k = 0; k < 32; k++) {
            size_t off = base + tid + k * 256;
            float s = g_states[off];
            g_states[off] = Hreg[k];
            Hreg[k] = dec * Hreg[k] + s;
        }
    }
}

// ---------------- Y_off = exp(Acs[l]) * C @ state^T ; Yd += Y_off + x*D ----------------
__global__ __launch_bounds__(256) void yoff_kernel(const float* __restrict__ Dv) {
    int b = blockIdx.x;
    int h = b & 31, c = (b >> 5) & 31, dir = b >> 10;
    int tid = threadIdx.x;
    __shared__ float sAcs[CHK];
    __shared__ float sC[CHK][17];
    __shared__ float sS[64][17];
    if (tid < CHK) sAcs[tid] = g_Acs[(b << 7) + tid];
    __syncthreads();
    const float* Cp = g_Cm + ((size_t)(dir * L + c * CHK)) * NST;
    const float* Sp = g_states + ((size_t)b << 13);
    int tx = tid & 15, ty = tid >> 4;
    float acc[8][4] = {};
    int l0 = tid >> 1, nkb = (tid & 1) * 8;
    int p1 = tid >> 2, nkb2 = (tid & 3) * 4;
    for (int nt = 0; nt < 8; nt++) {
#pragma unroll
        for (int i = 0; i < 8; i++)
            sC[l0][nkb + i] = Cp[(size_t)l0 * NST + nt * 16 + nkb + i];
        {
            float4 v = *(const float4*)(Sp + (size_t)p1 * NST + nt * 16 + nkb2);
            sS[p1][nkb2] = v.x; sS[p1][nkb2 + 1] = v.y;
            sS[p1][nkb2 + 2] = v.z; sS[p1][nkb2 + 3] = v.w;
        }
        __syncthreads();
#pragma unroll
        for (int nk = 0; nk < 16; nk++) {
            float sv0 = sS[tx * 4][nk], sv1 = sS[tx * 4 + 1][nk];
            float sv2 = sS[tx * 4 + 2][nk], sv3 = sS[tx * 4 + 3][nk];
#pragma unroll
            for (int i = 0; i < 8; i++) {
                float cv = sC[ty * 8 + i][nk];
                acc[i][0] += cv * sv0; acc[i][1] += cv * sv1;
                acc[i][2] += cv * sv2; acc[i][3] += cv * sv3;
            }
        }
        __syncthreads();
    }
    float Dh = Dv[h];
    float* Yp = g_Yd + ((size_t)(dir * L + c * CHK)) * DIN + h * HD;
#pragma unroll
    for (int i = 0; i < 8; i++) {
        int l = ty * 8 + i;
        float e = expf(sAcs[l]);
        int tglob = c * CHK + l;
        int ts = dir ? (L - 1 - tglob) : tglob;
        const float* xrow = g_xc + (size_t)ts * CONVD + h * HD;
#pragma unroll
        for (int j = 0; j < 4; j++) {
            int p = tx * 4 + j;
            size_t o = (size_t)l * DIN + p;
            Yp[o] = Yp[o] + e * acc[i][j] + xrow[p] * Dh;
        }
    }
}

// ---------------- fd[t,h] = x_og[t] . fc_D_w[h] + D[h] ----------------
__global__ void fcD_kernel(const float* __restrict__ W, const float* __restrict__ Dv) {
    int t = blockIdx.x;
    __shared__ float sx[DIN];
    int tid = threadIdx.x;
#pragma unroll
    for (int k = 0; k < 8; k++) sx[tid + k * 256] = g_xc[(size_t)t * CONVD + tid + k * 256];
    __syncthreads();
    int warp = tid >> 5, lane = tid & 31;
    for (int q = 0; q < 4; q++) {
        int h = warp * 4 + q;
        const float* wr = W + (size_t)h * DIN;
        float acc = 0.f;
        for (int i = 0; i < 64; i++) {
            int d = i * 32 + lane;
            acc += sx[d] * wr[d];
        }
        for (int o = 16; o > 0; o >>= 1) acc += __shfl_down_sync(0xffffffffu, acc, o);
        if (lane == 0) g_fd[t * NH + h] = acc + Dv[h];
    }
}

// ---------------- shift + merge dirs + skip + gate + RMSNorm -> fp16 hi/lo ----------------
__global__ void combine_kernel(const float* __restrict__ norm_w) {
    int t = blockIdx.x;
    int tid = threadIdx.x;
    __shared__ float red[256];
    __shared__ float sc;
    float yg[8];
    float ss = 0.f;
#pragma unroll
    for (int k = 0; k < 8; k++) {
        int d = tid + k * 256;
        float yfw = (t > 0) ? g_Yd[((size_t)(t - 1)) * DIN + d] : 0.f;
        float ybw = (t < L - 1) ? g_Yd[((size_t)(L + (L - 2 - t))) * DIN + d] : 0.f;
        float x = g_xc[(size_t)t * CONVD + d];
        float fdv = g_fd[t * NH + (d >> 6)];
        float z = g_zx[(size_t)t * DPROJ + d];
        float v = (yfw + ybw + x * fdv) * (z * sigmoidf_(z));
        yg[k] = v;
        ss += v * v;
    }
    red[tid] = ss;
    __syncthreads();
    for (int o = 128; o > 0; o >>= 1) {
        if (tid < o) red[tid] += red[tid + o];
        __syncthreads();
    }
    if (tid == 0) sc = rsqrtf(red[0] * (1.f / DIN) + EPSV);
    __syncthreads();
    float s = sc;
#pragma unroll
    for (int k = 0; k < 8; k++) {
        int d = tid + k * 256;
        float v = yg[k] * s * norm_w[d];
        __half hv, lv;
        split_hilo_h(v, hv, lv);
        g_ynh[(size_t)t * DIN + d] = hv;
        g_ynl[(size_t)t * DIN + d] = lv;
    }
}

extern "C" void kernel_launch(void* const* d_in, const int* in_sizes, int n_in,
                              void* d_out, int out_size) {
    const float* u          = (const float*)d_in[0];
    const float* in_proj_w  = (const float*)d_in[1];
    const float* conv_w     = (const float*)d_in[2];
    const float* conv_b     = (const float*)d_in[3];
    const float* dt_bias    = (const float*)d_in[4];
    const float* A_log      = (const float*)d_in[5];
    const float* Dv         = (const float*)d_in[6];
    const float* fc_D_w     = (const float*)d_in[7];
    const float* norm_w     = (const float*)d_in[8];
    const float* out_proj_w = (const float*)d_in[9];
    float* out = (float*)d_out;

    float *zx, *Bm, *Cm, *G;
    __half *uh, *ul, *wi, *ynh, *ynl, *wo;
    cudaGetSymbolAddress((void**)&zx, g_zx);
    cudaGetSymbolAddress((void**)&Bm, g_Bm);
    cudaGetSymbolAddress((void**)&Cm, g_Cm);
    cudaGetSymbolAddress((void**)&G, g_G);
    cudaGetSymbolAddress((void**)&uh, g_uh);
    cudaGetSymbolAddress((void**)&ul, g_ul);
    cudaGetSymbolAddress((void**)&wi, g_wi);
    cudaGetSymbolAddress((void**)&ynh, g_ynh);
    cudaGetSymbolAddress((void**)&ynl, g_ynl);
    cudaGetSymbolAddress((void**)&wo, g_wo);

    const int smemB = 2 * 3 * 128 * APAD * 2;  // 61440 B
    cudaFuncSetAttribute(gemm_2t, cudaFuncAttributeMaxDynamicSharedMemorySize, smemB);

    // 0) convert: activations fp16 hi/lo, weights single fp16
    cvt_hilo_kernel<<<((size_t)L * DM + 255) / 256, 256>>>(u, uh, ul, (size_t)L * DM);
    cvt_h_kernel<<<((size_t)DPROJ * DM + 255) / 256, 256>>>(in_proj_w, wi, (size_t)DPROJ * DM);
    cvt_h_kernel<<<((size_t)DM * DIN + 255) / 256, 256>>>(out_proj_w, wo, (size_t)DM * DIN);

    // 1) in_proj: (4096 x 1024) @ (4672 x 1024)^T  -- fp16 2-term
    gemm_2t<<<dim3((DPROJ + 127) / 128, L / 128), 256, smemB>>>(uh, ul, wi, zx, DPROJ, DM);
    // 2) conv + silu
    conv_kernel<<<((size_t)L * CONVD + 255) / 256, 256>>>(conv_w, conv_b);
    // 3) dt softplus
    dt_kernel<<<(2 * L * NH + 255) / 256, 256>>>(dt_bias);
    // 4) B/C and x*dt prep
    prep_bc_kernel<<<(2 * L * NST + 255) / 256, 256>>>();
    prep_x_kernel<<<((size_t)2 * L * DIN + 255) / 256, 256>>>();
    // 5) per-chunk cumsum of A*dt
    acs_kernel<<<dim3(NC, 2), 32>>>(A_log);
    // 6) G = C B^T per (dir,chunk)
    sgemm_nt<<<dim3(1, 1, 2 * NC), 256>>>(Cm, Bm, G, CHK, CHK, NST,
                                          CHK * NST, CHK * NST, CHK * CHK);
    // 7) Y_diag + chunk states
    ydiag_states_kernel<<<2 * NC * NH, 256>>>();
    // 8) inter-chunk recurrence
    recur_kernel<<<2 * NH, 256>>>();
    // 9) Y_off + x*D
    yoff_kernel<<<2 * NC * NH, 256>>>(Dv);
    // 10) fd
    fcD_kernel<<<L, 256>>>(fc_D_w, Dv);
    // 11) shift/merge/gate/RMSNorm (writes fp16 hi/lo)
    combine_kernel<<<L, 256>>>(norm_w);
    // 12) out_proj: (4096 x 2048) @ (1024 x 2048)^T -- fp16 2-term
    gemm_2t<<<dim3(DM / 128, L / 128), 256, smemB>>>(ynh, ynl, wo, out, DM, DIN);
}

// round 7
// speedup vs baseline: 1.4930x; 1.2043x over previous
#include <cuda_runtime.h>
#include <cuda_bf16.h>
#include <cuda_fp16.h>
#include <math.h>
#include <stdint.h>

#define L 4096
#define DM 1024
#define DIN 2048
#define NH 32
#define HD 64
#define NST 128
#define CONVD 2560
#define DPROJ 4672
#define CHK 128
#define NC 32
#define EPSV 1e-5f

// ---------------- scratch (static device globals; no allocation) ----------------
__device__ float g_zx[(size_t)L * DPROJ];        // in_proj output (4096 x 4672)
__device__ float g_xc[(size_t)L * CONVD];        // conv+silu output (x_og | BC)
__device__ float g_dt2[2 * L * NH];              // softplus dt, both dirs
__device__ float g_Bm[(size_t)2 * L * NST];      // B per dir (flipped for dir1)
__device__ float g_Cm[(size_t)2 * L * NST];      // C per dir
__device__ float g_Acs[2 * NC * NH * CHK];       // per-chunk cumsum of A*dt
__device__ float g_G[(size_t)2 * NC * CHK * CHK];// C B^T per (dir,chunk)
__device__ float g_Yd[(size_t)2 * L * DIN];      // Y (diag then += off + x*D)
__device__ float g_states[(size_t)2 * NC * NH * HD * NST];
__device__ float g_fd[L * NH];

// fp16 buffers for tensor-core GEMMs (A split hi/lo, weights single fp16)
__device__ __align__(16) __half g_uh[(size_t)L * DM];
__device__ __align__(16) __half g_ul[(size_t)L * DM];
__device__ __align__(16) __half g_wi[(size_t)DPROJ * DM];
__device__ __align__(16) __half g_ynh[(size_t)L * DIN];
__device__ __align__(16) __half g_ynl[(size_t)L * DIN];
__device__ __align__(16) __half g_wo[(size_t)DM * DIN];

__device__ __forceinline__ float sigmoidf_(float x) { return 1.f / (1.f + expf(-x)); }

__device__ __forceinline__ uint32_t smem_u32(const void* p) {
    uint32_t a;
    asm("{ .reg .u64 tmp; cvta.to.shared.u64 tmp, %1; cvt.u32.u64 %0, tmp; }" : "=r"(a) : "l"(p));
    return a;
}
__device__ __forceinline__ void cp_async16(uint32_t dst, const void* src, int srcsize) {
    asm volatile("cp.async.cg.shared.global [%0], [%1], 16, %2;"
                 :: "r"(dst), "l"(src), "r"(srcsize));
}
#define CP_COMMIT() asm volatile("cp.async.commit_group;" ::: "memory")
#define CP_WAIT1()  asm volatile("cp.async.wait_group 1;"  ::: "memory")
#define CP_WAIT0()  asm volatile("cp.async.wait_group 0;"  ::: "memory")

__device__ __forceinline__ void ldsm4(uint32_t* r, uint32_t addr) {
    asm volatile("ldmatrix.sync.aligned.m8n8.x4.shared.b16 {%0,%1,%2,%3}, [%4];"
                 : "=r"(r[0]), "=r"(r[1]), "=r"(r[2]), "=r"(r[3]) : "r"(addr));
}
__device__ __forceinline__ void mma16816h(float* c, const uint32_t* a, uint32_t b0, uint32_t b1) {
    asm volatile("mma.sync.aligned.m16n8k16.row.col.f32.f16.f16.f32 "
                 "{%0,%1,%2,%3}, {%4,%5,%6,%7}, {%8,%9}, {%0,%1,%2,%3};"
                 : "+f"(c[0]), "+f"(c[1]), "+f"(c[2]), "+f"(c[3])
                 : "r"(a[0]), "r"(a[1]), "r"(a[2]), "r"(a[3]), "r"(b0), "r"(b1));
}
__device__ __forceinline__ void split_hilo_h(float v, __half& h, __half& l) {
    h = __float2half(v);
    l = __float2half(v - __half2float(h));
}

// ---------------- fp32 -> fp16 hi/lo split (activations) ----------------
__global__ void cvt_hilo_kernel(const float* __restrict__ x,
                                __half* __restrict__ hi,
                                __half* __restrict__ lo, size_t n) {
    size_t i = (size_t)blockIdx.x * blockDim.x + threadIdx.x;
    if (i >= n) return;
    __half h, lv;
    split_hilo_h(x[i], h, lv);
    hi[i] = h; lo[i] = lv;
}
// ---------------- fp32 -> single fp16 (weights) ----------------
__global__ void cvt_h_kernel(const float* __restrict__ x, __half* __restrict__ o, size_t n) {
    size_t i = (size_t)blockIdx.x * blockDim.x + threadIdx.x;
    if (i >= n) return;
    o[i] = __float2half(x[i]);
}

// ===== mma.sync fp16 2-term GEMM: C[m,n] = sum_k (Ah+Al)[m,k]*B[n,k] =====
#define KC 32
#define APAD 40   // smem row stride in halfs (80B, ldmatrix conflict-free)

__global__ __launch_bounds__(256, 2) void gemm_2t(
    const __half* __restrict__ Ah, const __half* __restrict__ Al,
    const __half* __restrict__ Bw,
    float* __restrict__ Cc, int Ntot, int Ktot) {
    extern __shared__ __align__(16) __half sm[];
    const int tid = threadIdx.x;
    const int bRow = blockIdx.y * 128, bCol = blockIdx.x * 128;
    const int wid = tid >> 5, lane = tid & 31;
    const int wm = (wid >> 2) * 64, wn = (wid & 3) * 32;

    __half* sp[2][3];
#pragma unroll
    for (int s = 0; s < 2; s++)
#pragma unroll
        for (int o = 0; o < 3; o++) sp[s][o] = sm + ((s * 3 + o) * 128 * APAD);

    float acc[4][4][4];
#pragma unroll
    for (int i = 0; i < 4; i++)
#pragma unroll
        for (int j = 0; j < 4; j++)
#pragma unroll
            for (int q = 0; q < 4; q++) acc[i][j][q] = 0.f;

    const int nst = Ktot / KC;

    auto issue = [&](int s, int c) {
        int kt = c * KC;
#pragma unroll
        for (int i = 0; i < 2; i++) {
            int u = tid + i * 256;
            int r = u >> 2, kc = (u & 3) * 8;
            size_t ga = (size_t)(bRow + r) * Ktot + kt + kc;
            cp_async16(smem_u32(sp[s][0] + r * APAD + kc), Ah + ga, 16);
            cp_async16(smem_u32(sp[s][1] + r * APAD + kc), Al + ga, 16);
            int ok = (bCol + r) < Ntot ? 16 : 0;
            size_t gb = ok ? ((size_t)(bCol + r) * Ktot + kt + kc) : 0;
            cp_async16(smem_u32(sp[s][2] + r * APAD + kc), Bw + gb, ok);
        }
    };

    issue(0, 0);
    CP_COMMIT();

    const int ar = lane & 15, ac = (lane >> 4) * 8;
    for (int c = 0; c < nst; c++) {
        if (c + 1 < nst) { issue((c + 1) & 1, c + 1); CP_COMMIT(); CP_WAIT1(); }
        else CP_WAIT0();
        __syncthreads();
        const __half* sa_h = sp[c & 1][0];
        const __half* sa_l = sp[c & 1][1];
        const __half* sb   = sp[c & 1][2];
#pragma unroll
        for (int kk = 0; kk < 2; kk++) {
            int k0 = kk * 16;
            uint32_t bf[2][4];
#pragma unroll
            for (int bt = 0; bt < 2; bt++)
                ldsm4(bf[bt], smem_u32(sb + (wn + bt * 16 + ar) * APAD + k0 + ac));
#pragma unroll
            for (int mt = 0; mt < 4; mt++) {
                uint32_t afh[4], afl[4];
                ldsm4(afh, smem_u32(sa_h + (wm + mt * 16 + ar) * APAD + k0 + ac));
                ldsm4(afl, smem_u32(sa_l + (wm + mt * 16 + ar) * APAD + k0 + ac));
#pragma unroll
                for (int nt = 0; nt < 4; nt++) {
                    int bt = nt >> 1, sel = nt & 1;
                    mma16816h(acc[mt][nt], afh, bf[bt][sel], bf[bt][sel + 2]);
                }
#pragma unroll
                for (int nt = 0; nt < 4; nt++) {
                    int bt = nt >> 1, sel = nt & 1;
                    mma16816h(acc[mt][nt], afl, bf[bt][sel], bf[bt][sel + 2]);
                }
            }
        }
        __syncthreads();
    }

    const int g = lane >> 2, t4 = lane & 3;
#pragma unroll
    for (int mt = 0; mt < 4; mt++) {
#pragma unroll
        for (int nt = 0; nt < 4; nt++) {
            int row = bRow + wm + mt * 16 + g;
            int col = bCol + wn + nt * 8 + t4 * 2;
            if (col < Ntot) {
                float* p0 = Cc + (size_t)row * Ntot + col;
                p0[0] = acc[mt][nt][0];
                p0[1] = acc[mt][nt][1];
                float* p1 = p0 + (size_t)8 * Ntot;
                p1[0] = acc[mt][nt][2];
                p1[1] = acc[mt][nt][3];
            }
        }
    }
}

// ---------------- generic NT SGEMM (small batched G = C B^T) --------
__global__ __launch_bounds__(256) void sgemm_nt(const float* __restrict__ A,
                                                const float* __restrict__ B,
                                                float* __restrict__ C,
                                                int M, int N, int K,
                                                long sA, long sB, long sC) {
    A += (size_t)blockIdx.z * sA;
    B += (size_t)blockIdx.z * sB;
    C += (size_t)blockIdx.z * sC;
    __shared__ float As[16][128];
    __shared__ float Bs[16][128];
    int tid = threadIdx.x;
    int bRow = blockIdx.y * 128, bCol = blockIdx.x * 128;
    int tx = tid & 15, ty = tid >> 4;
    float acc[8][8] = {};
    int lr = tid >> 2;
    int lk = (tid & 3) * 4;
    for (int kt = 0; kt < K; kt += 16) {
#pragma unroll
        for (int p = 0; p < 2; p++) {
            int r = lr + p * 64;
            int row = bRow + r;
            float4 v = make_float4(0.f, 0.f, 0.f, 0.f);
            if (row < M) v = *(const float4*)(A + (size_t)row * K + kt + lk);
            As[lk][r] = v.x; As[lk + 1][r] = v.y; As[lk + 2][r] = v.z; As[lk + 3][r] = v.w;
            int col = bCol + r;
            float4 w = make_float4(0.f, 0.f, 0.f, 0.f);
            if (col < N) w = *(const float4*)(B + (size_t)col * K + kt + lk);
            Bs[lk][r] = w.x; Bs[lk + 1][r] = w.y; Bs[lk + 2][r] = w.z; Bs[lk + 3][r] = w.w;
        }
        __syncthreads();
#pragma unroll
        for (int k = 0; k < 16; k++) {
            float ra[8], rb[8];
            *(float4*)ra       = *(const float4*)&As[k][ty * 8];
            *(float4*)(ra + 4) = *(const float4*)&As[k][ty * 8 + 4];
            *(float4*)rb       = *(const float4*)&Bs[k][tx * 8];
            *(float4*)(rb + 4) = *(const float4*)&Bs[k][tx * 8 + 4];
#pragma unroll
            for (int i = 0; i < 8; i++)
#pragma unroll
                for (int j = 0; j < 8; j++)
                    acc[i][j] += ra[i] * rb[j];
        }
        __syncthreads();
    }
    for (int i = 0; i < 8; i++) {
        int row = bRow + ty * 8 + i;
        if (row >= M) continue;
        for (int j = 0; j < 8; j++) {
            int col = bCol + tx * 8 + j;
            if (col < N) C[(size_t)row * N + col] = acc[i][j];
        }
    }
}

// ---------------- depthwise causal conv (k=4) + bias + silu ----------------
__global__ void conv_kernel(const float* __restrict__ cw, const float* __restrict__ cb) {
    size_t idx = (size_t)blockIdx.x * blockDim.x + threadIdx.x;
    if (idx >= (size_t)L * CONVD) return;
    int c = (int)(idx % CONVD);
    int t = (int)(idx / CONVD);
    float acc = cb[c];
#pragma unroll
    for (int k = 0; k < 4; k++) {
        int ts = t - 3 + k;
        if (ts >= 0) acc += cw[c * 4 + k] * g_zx[(size_t)ts * DPROJ + DIN + c];
    }
    g_xc[idx] = acc * sigmoidf_(acc);
}

// ---------------- dt (with direction flip) + softplus ----------------
__global__ void dt_kernel(const float* __restrict__ dt_bias) {
    int idx = blockIdx.x * blockDim.x + threadIdx.x;
    if (idx >= 2 * L * NH) return;
    int h = idx & 31;
    int t = (idx >> 5) & (L - 1);
    int dir = idx >> 17;
    int ts = dir ? (L - 1 - t) : t;
    float v = g_zx[(size_t)ts * DPROJ + DIN + CONVD + dir * NH + h] + dt_bias[h];
    g_dt2[idx] = (v > 20.f) ? v : log1pf(expf(v));
}

// ---------------- B/C split per direction (flip for dir1) ----------------
__global__ void prep_bc_kernel() {
    int idx = blockIdx.x * blockDim.x + threadIdx.x;
    if (idx >= 2 * L * NST) return;
    int n = idx & 127;
    int t = (idx >> 7) & (L - 1);
    int dir = idx >> 19;
    int ts = dir ? (L - 1 - t) : t;
    int off = dir ? 256 : 0;
    const float* p = g_xc + (size_t)ts * CONVD + DIN + off;
    g_Bm[idx] = p[n];
    g_Cm[idx] = p[NST + n];
}

// ---------------- per-chunk cumsum of A*dt ----------------
__global__ void acs_kernel(const float* __restrict__ A_log) {
    int c = blockIdx.x, dir = blockIdx.y, h = threadIdx.x;
    float Ah = -expf(A_log[h]);
    float cum = 0.f;
    float* out = g_Acs + (((dir * NC + c) * NH + h) << 7);
    const float* dtp = g_dt2 + ((size_t)(dir * L + c * CHK)) * NH + h;
    for (int l = 0; l < CHK; l++) {
        cum += Ah * dtp[l * NH];
        out[l] = cum;
    }
}

// ---------------- per (dir,chunk,head): Y_diag = (G.*Lmat)@xdt ; states = B^T @ (decay.*xdt) ----
// xdt built on the fly: x from g_xc (dir-flipped row) * dt (per-row scalar from g_dt2)
__global__ __launch_bounds__(256) void ydiag_states_kernel() {
    int b = blockIdx.x;
    int h = b & 31, c = (b >> 5) & 31, dir = b >> 10;
    int tid = threadIdx.x;
    __shared__ float sAcs[CHK];
    __shared__ float sDt[CHK];
    __shared__ float sMl[CHK][17];
    __shared__ float sXs[16][68];
    __shared__ float sB[16][132];
    __shared__ float sXd[16][68];
    if (tid < CHK) {
        sAcs[tid] = g_Acs[(b << 7) + tid];
        sDt[tid] = g_dt2[((size_t)(dir * L + c * CHK + tid)) * NH + h];
    }
    __syncthreads();
    const float* Gp = g_G + ((size_t)(dir * NC + c) << 14);
    int tx = tid & 15, ty = tid >> 4;
    float acc[8][4] = {};
    int l0 = tid >> 1, skb = (tid & 1) * 8;
    for (int st = 0; st < 8; st++) {
#pragma unroll
        for (int i = 0; i < 8; i++) {
            int s = st * 16 + skb + i;
            float g = Gp[l0 * CHK + s];
            sMl[l0][skb + i] = (l0 >= s) ? g * expf(sAcs[l0] - sAcs[s]) : 0.f;
        }
        {
            int sk = tid >> 4, p0 = (tid & 15) * 4;
            int l = st * 16 + sk;
            int tg = c * CHK + l;
            int ts = dir ? (L - 1 - tg) : tg;
            float dtv = sDt[l];
            float4 v = *(const float4*)(g_xc + (size_t)ts * CONVD + h * HD + p0);
            sXs[sk][p0] = v.x * dtv; sXs[sk][p0 + 1] = v.y * dtv;
            sXs[sk][p0 + 2] = v.z * dtv; sXs[sk][p0 + 3] = v.w * dtv;
        }
        __syncthreads();
#pragma unroll
        for (int sk = 0; sk < 16; sk++) {
            float xb0 = sXs[sk][tx * 4], xb1 = sXs[sk][tx * 4 + 1];
            float xb2 = sXs[sk][tx * 4 + 2], xb3 = sXs[sk][tx * 4 + 3];
#pragma unroll
            for (int i = 0; i < 8; i++) {
                float m = sMl[ty * 8 + i][sk];
                acc[i][0] += m * xb0; acc[i][1] += m * xb1;
                acc[i][2] += m * xb2; acc[i][3] += m * xb3;
            }
        }
        __syncthreads();
    }
    float* Yp = g_Yd + ((size_t)(dir * L + c * CHK)) * DIN + h * HD;
#pragma unroll
    for (int i = 0; i < 8; i++)
#pragma unroll
        for (int j = 0; j < 4; j++)
            Yp[(size_t)(ty * 8 + i) * DIN + tx * 4 + j] = acc[i][j];

    // ---- states ----
    float accS[8][4] = {};
    int n0 = (tid & 31) * 4;
    int p0s = (tid >> 5) * 8;
    float lastA = sAcs[127];
    const float* Bp = g_Bm + ((size_t)(dir * L + c * CHK)) * NST;
    for (int lt = 0; lt < 8; lt++) {
        {
            int lk = tid >> 4, nb = (tid & 15) * 8;
            float4 v0 = *(const float4*)(Bp + (size_t)(lt * 16 + lk) * NST + nb);
            float4 v1 = *(const float4*)(Bp + (size_t)(lt * 16 + lk) * NST + nb + 4);
            sB[lk][nb] = v0.x; sB[lk][nb + 1] = v0.y; sB[lk][nb + 2] = v0.z; sB[lk][nb + 3] = v0.w;
            sB[lk][nb + 4] = v1.x; sB[lk][nb + 5] = v1.y; sB[lk][nb + 6] = v1.z; sB[lk][nb + 7] = v1.w;
            int pb = (tid & 15) * 4;
            int l = lt * 16 + lk;
            int tg = c * CHK + l;
            int ts = dir ? (L - 1 - tg) : tg;
            float dec = expf(lastA - sAcs[l]) * sDt[l];
            float4 xv = *(const float4*)(g_xc + (size_t)ts * CONVD + h * HD + pb);
            sXd[lk][pb] = xv.x * dec; sXd[lk][pb + 1] = xv.y * dec;
            sXd[lk][pb + 2] = xv.z * dec; sXd[lk][pb + 3] = xv.w * dec;
        }
        __syncthreads();
#pragma unroll
        for (int lk2 = 0; lk2 < 16; lk2++) {
            float pv[8];
#pragma unroll
            for (int i = 0; i < 8; i++) pv[i] = sXd[lk2][p0s + i];
            float nv0 = sB[lk2][n0], nv1 = sB[lk2][n0 + 1];
            float nv2 = sB[lk2][n0 + 2], nv3 = sB[lk2][n0 + 3];
#pragma unroll
            for (int i = 0; i < 8; i++) {
                accS[i][0] += pv[i] * nv0; accS[i][1] += pv[i] * nv1;
                accS[i][2] += pv[i] * nv2; accS[i][3] += pv[i] * nv3;
            }
        }
        __syncthreads();
    }
    float* Sp = g_states + ((size_t)b << 13);
#pragma unroll
    for (int i = 0; i < 8; i++)
#pragma unroll
        for (int j = 0; j < 4; j++)
            Sp[(size_t)(p0s + i) * NST + n0 + j] = accS[i][j];
}

// ---------------- inter-chunk recurrence (8-way split per (dir,h)) ----------------
__global__ void recur_kernel() {
    int bi = blockIdx.x;               // 0..511
    int seg = bi & 7, hh = bi >> 3;
    int dir = hh >> 5, h = hh & 31;
    int tid = threadIdx.x;
    float Hreg[4] = {0.f, 0.f, 0.f, 0.f};
    for (int c = 0; c < NC; c++) {
        int sb = (dir * NC + c) * NH + h;
        float dec = __expf(g_Acs[(sb << 7) + 127]);
        size_t base = ((size_t)sb << 13) + seg * 1024;
#pragma unroll
        for (int k = 0; k < 4; k++) {
            size_t off = base + tid + k * 256;
            float s = g_states[off];
            g_states[off] = Hreg[k];
            Hreg[k] = dec * Hreg[k] + s;
        }
    }
}

// ---------------- Y_off = exp(Acs[l]) * C @ state^T ; Yd += Y_off + x*D ----------------
__global__ __launch_bounds__(256) void yoff_kernel(const float* __restrict__ Dv) {
    int b = blockIdx.x;
    int h = b & 31, c = (b >> 5) & 31, dir = b >> 10;
    int tid = threadIdx.x;
    __shared__ float sAcs[CHK];
    __shared__ float sC[CHK][17];
    __shared__ float sS[64][17];
    if (tid < CHK) sAcs[tid] = g_Acs[(b << 7) + tid];
    __syncthreads();
    const float* Cp = g_Cm + ((size_t)(dir * L + c * CHK)) * NST;
    const float* Sp = g_states + ((size_t)b << 13);
    int tx = tid & 15, ty = tid >> 4;
    float acc[8][4] = {};
    int l0 = tid >> 1, nkb = (tid & 1) * 8;
    int p1 = tid >> 2, nkb2 = (tid & 3) * 4;
    for (int nt = 0; nt < 8; nt++) {
#pragma unroll
        for (int i = 0; i < 8; i++)
            sC[l0][nkb + i] = Cp[(size_t)l0 * NST + nt * 16 + nkb + i];
        {
            float4 v = *(const float4*)(Sp + (size_t)p1 * NST + nt * 16 + nkb2);
            sS[p1][nkb2] = v.x; sS[p1][nkb2 + 1] = v.y;
            sS[p1][nkb2 + 2] = v.z; sS[p1][nkb2 + 3] = v.w;
        }
        __syncthreads();
#pragma unroll
        for (int nk = 0; nk < 16; nk++) {
            float sv0 = sS[tx * 4][nk], sv1 = sS[tx * 4 + 1][nk];
            float sv2 = sS[tx * 4 + 2][nk], sv3 = sS[tx * 4 + 3][nk];
#pragma unroll
            for (int i = 0; i < 8; i++) {
                float cv = sC[ty * 8 + i][nk];
                acc[i][0] += cv * sv0; acc[i][1] += cv * sv1;
                acc[i][2] += cv * sv2; acc[i][3] += cv * sv3;
            }
        }
        __syncthreads();
    }
    float Dh = Dv[h];
    float* Yp = g_Yd + ((size_t)(dir * L + c * CHK)) * DIN + h * HD;
#pragma unroll
    for (int i = 0; i < 8; i++) {
        int l = ty * 8 + i;
        float e = expf(sAcs[l]);
        int tglob = c * CHK + l;
        int ts = dir ? (L - 1 - tglob) : tglob;
        const float* xrow = g_xc + (size_t)ts * CONVD + h * HD;
#pragma unroll
        for (int j = 0; j < 4; j++) {
            int p = tx * 4 + j;
            size_t o = (size_t)l * DIN + p;
            Yp[o] = Yp[o] + e * acc[i][j] + xrow[p] * Dh;
        }
    }
}

// ---------------- fd = x_og @ fc_D_w^T + D, tiled (32 t-rows per block) ----------------
__global__ __launch_bounds__(256) void fcD_kernel(const float* __restrict__ W,
                                                  const float* __restrict__ Dv) {
    int t0 = blockIdx.x * 32;
    __shared__ float sx[32][132];
    __shared__ float sW[32][132];
    int tid = threadIdx.x;
    int tx = tid & 15, ty = tid >> 4;
    float acc[2][2] = {};
    for (int kc = 0; kc < DIN; kc += 128) {
#pragma unroll
        for (int i = 0; i < 4; i++) {
            int u = tid + i * 256;          // 0..1023
            int r = u >> 5, k4 = (u & 31) * 4;
            *(float4*)&sx[r][k4] = *(const float4*)(g_xc + (size_t)(t0 + r) * CONVD + kc + k4);
            *(float4*)&sW[r][k4] = *(const float4*)(W + (size_t)r * DIN + kc + k4);
        }
        __syncthreads();
#pragma unroll 8
        for (int k4 = 0; k4 < 128; k4 += 4) {
            float4 x0 = *(float4*)&sx[ty * 2][k4];
            float4 x1 = *(float4*)&sx[ty * 2 + 1][k4];
            float4 w0 = *(float4*)&sW[tx * 2][k4];
            float4 w1 = *(float4*)&sW[tx * 2 + 1][k4];
            acc[0][0] += x0.x * w0.x + x0.y * w0.y + x0.z * w0.z + x0.w * w0.w;
            acc[0][1] += x0.x * w1.x + x0.y * w1.y + x0.z * w1.z + x0.w * w1.w;
            acc[1][0] += x1.x * w0.x + x1.y * w0.y + x1.z * w0.z + x1.w * w0.w;
            acc[1][1] += x1.x * w1.x + x1.y * w1.y + x1.z * w1.z + x1.w * w1.w;
        }
        __syncthreads();
    }
#pragma unroll
    for (int i = 0; i < 2; i++)
#pragma unroll
        for (int j = 0; j < 2; j++)
            g_fd[(t0 + ty * 2 + i) * NH + tx * 2 + j] = acc[i][j] + Dv[tx * 2 + j];
}

// ---------------- shift + merge dirs + skip + gate + RMSNorm -> fp16 hi/lo ----------------
__global__ void combine_kernel(const float* __restrict__ norm_w) {
    int t = blockIdx.x;
    int tid = threadIdx.x;
    __shared__ float red[256];
    __shared__ float sc;
    float yg[8];
    float ss = 0.f;
#pragma unroll
    for (int k = 0; k < 8; k++) {
        int d = tid + k * 256;
        float yfw = (t > 0) ? g_Yd[((size_t)(t - 1)) * DIN + d] : 0.f;
        float ybw = (t < L - 1) ? g_Yd[((size_t)(L + (L - 2 - t))) * DIN + d] : 0.f;
        float x = g_xc[(size_t)t * CONVD + d];
        float fdv = g_fd[t * NH + (d >> 6)];
        float z = g_zx[(size_t)t * DPROJ + d];
        float v = (yfw + ybw + x * fdv) * (z * sigmoidf_(z));
        yg[k] = v;
        ss += v * v;
    }
    red[tid] = ss;
    __syncthreads();
    for (int o = 128; o > 0; o >>= 1) {
        if (tid < o) red[tid] += red[tid + o];
        __syncthreads();
    }
    if (tid == 0) sc = rsqrtf(red[0] * (1.f / DIN) + EPSV);
    __syncthreads();
    float s = sc;
#pragma unroll
    for (int k = 0; k < 8; k++) {
        int d = tid + k * 256;
        float v = yg[k] * s * norm_w[d];
        __half hv, lv;
        split_hilo_h(v, hv, lv);
        g_ynh[(size_t)t * DIN + d] = hv;
        g_ynl[(size_t)t * DIN + d] = lv;
    }
}

extern "C" void kernel_launch(void* const* d_in, const int* in_sizes, int n_in,
                              void* d_out, int out_size) {
    const float* u          = (const float*)d_in[0];
    const float* in_proj_w  = (const float*)d_in[1];
    const float* conv_w     = (const float*)d_in[2];
    const float* conv_b     = (const float*)d_in[3];
    const float* dt_bias    = (const float*)d_in[4];
    const float* A_log      = (const float*)d_in[5];
    const float* Dv         = (const float*)d_in[6];
    const float* fc_D_w     = (const float*)d_in[7];
    const float* norm_w     = (const float*)d_in[8];
    const float* out_proj_w = (const float*)d_in[9];
    float* out = (float*)d_out;

    float *zx, *Bm, *Cm, *G;
    __half *uh, *ul, *wi, *ynh, *ynl, *wo;
    cudaGetSymbolAddress((void**)&zx, g_zx);
    cudaGetSymbolAddress((void**)&Bm, g_Bm);
    cudaGetSymbolAddress((void**)&Cm, g_Cm);
    cudaGetSymbolAddress((void**)&G, g_G);
    cudaGetSymbolAddress((void**)&uh, g_uh);
    cudaGetSymbolAddress((void**)&ul, g_ul);
    cudaGetSymbolAddress((void**)&wi, g_wi);
    cudaGetSymbolAddress((void**)&ynh, g_ynh);
    cudaGetSymbolAddress((void**)&ynl, g_ynl);
    cudaGetSymbolAddress((void**)&wo, g_wo);

    const int smemB = 2 * 3 * 128 * APAD * 2;  // 61440 B
    cudaFuncSetAttribute(gemm_2t, cudaFuncAttributeMaxDynamicSharedMemorySize, smemB);

    // 0) convert: activations fp16 hi/lo, weights single fp16
    cvt_hilo_kernel<<<((size_t)L * DM + 255) / 256, 256>>>(u, uh, ul, (size_t)L * DM);
    cvt_h_kernel<<<((size_t)DPROJ * DM + 255) / 256, 256>>>(in_proj_w, wi, (size_t)DPROJ * DM);
    cvt_h_kernel<<<((size_t)DM * DIN + 255) / 256, 256>>>(out_proj_w, wo, (size_t)DM * DIN);

    // 1) in_proj
    gemm_2t<<<dim3((DPROJ + 127) / 128, L / 128), 256, smemB>>>(uh, ul, wi, zx, DPROJ, DM);
    // 2) conv + silu
    conv_kernel<<<((size_t)L * CONVD + 255) / 256, 256>>>(conv_w, conv_b);
    // 3) dt softplus
    dt_kernel<<<(2 * L * NH + 255) / 256, 256>>>(dt_bias);
    // 4) B/C prep
    prep_bc_kernel<<<(2 * L * NST + 255) / 256, 256>>>();
    // 5) per-chunk cumsum of A*dt
    acs_kernel<<<dim3(NC, 2), 32>>>(A_log);
    // 6) G = C B^T per (dir,chunk)
    sgemm_nt<<<dim3(1, 1, 2 * NC), 256>>>(Cm, Bm, G, CHK, CHK, NST,
                                          CHK * NST, CHK * NST, CHK * CHK);
    // 7) Y_diag + chunk states (xdt fused in)
    ydiag_states_kernel<<<2 * NC * NH, 256>>>();
    // 8) inter-chunk recurrence (8-way parallel)
    recur_kernel<<<512, 256>>>();
    // 9) Y_off + x*D
    yoff_kernel<<<2 * NC * NH, 256>>>(Dv);
    // 10) fd (tiled)
    fcD_kernel<<<L / 32, 256>>>(fc_D_w, Dv);
    // 11) shift/merge/gate/RMSNorm
    combine_kernel<<<L, 256>>>(norm_w);
    // 12) out_proj
    gemm_2t<<<dim3(DM / 128, L / 128), 256, smemB>>>(ynh, ynl, wo, out, DM, DIN);
}

// round 8
// speedup vs baseline: 1.5114x; 1.0123x over previous
#include <cuda_runtime.h>
#include <cuda_bf16.h>
#include <cuda_fp16.h>
#include <math.h>
#include <stdint.h>

#define L 4096
#define DM 1024
#define DIN 2048
#define NH 32
#define HD 64
#define NST 128
#define CONVD 2560
#define DPROJ 4672
#define CHK 128
#define NC 32
#define EPSV 1e-5f

// ---------------- scratch (static device globals; no allocation) ----------------
__device__ float g_zx[(size_t)L * DPROJ];
__device__ float g_xc[(size_t)L * CONVD];
__device__ float g_dt2[2 * L * NH];
__device__ float g_Bm[(size_t)2 * L * NST];
__device__ float g_Cm[(size_t)2 * L * NST];
__device__ float g_Acs[2 * NC * NH * CHK];
__device__ float g_G[(size_t)2 * NC * CHK * CHK];
__device__ float g_Yd[(size_t)2 * L * DIN];
__device__ float g_states[(size_t)2 * NC * NH * HD * NST];
__device__ float g_fd[L * NH];

__device__ __align__(16) __half g_uh[(size_t)L * DM];
__device__ __align__(16) __half g_ul[(size_t)L * DM];
__device__ __align__(16) __half g_wi[(size_t)DPROJ * DM];
__device__ __align__(16) __half g_ynh[(size_t)L * DIN];
__device__ __align__(16) __half g_ynl[(size_t)L * DIN];
__device__ __align__(16) __half g_wo[(size_t)DM * DIN];

__device__ __forceinline__ float sigmoidf_(float x) { return 1.f / (1.f + __expf(-x)); }

__device__ __forceinline__ uint32_t smem_u32(const void* p) {
    uint32_t a;
    asm("{ .reg .u64 tmp; cvta.to.shared.u64 tmp, %1; cvt.u32.u64 %0, tmp; }" : "=r"(a) : "l"(p));
    return a;
}
__device__ __forceinline__ void cp_async16(uint32_t dst, const void* src, int srcsize) {
    asm volatile("cp.async.cg.shared.global [%0], [%1], 16, %2;"
                 :: "r"(dst), "l"(src), "r"(srcsize));
}
#define CP_COMMIT() asm volatile("cp.async.commit_group;" ::: "memory")
#define CP_WAIT2()  asm volatile("cp.async.wait_group 2;"  ::: "memory")
#define CP_WAIT1()  asm volatile("cp.async.wait_group 1;"  ::: "memory")
#define CP_WAIT0()  asm volatile("cp.async.wait_group 0;"  ::: "memory")

__device__ __forceinline__ void ldsm4(uint32_t* r, uint32_t addr) {
    asm volatile("ldmatrix.sync.aligned.m8n8.x4.shared.b16 {%0,%1,%2,%3}, [%4];"
                 : "=r"(r[0]), "=r"(r[1]), "=r"(r[2]), "=r"(r[3]) : "r"(addr));
}
__device__ __forceinline__ void mma16816h(float* c, const uint32_t* a, uint32_t b0, uint32_t b1) {
    asm volatile("mma.sync.aligned.m16n8k16.row.col.f32.f16.f16.f32 "
                 "{%0,%1,%2,%3}, {%4,%5,%6,%7}, {%8,%9}, {%0,%1,%2,%3};"
                 : "+f"(c[0]), "+f"(c[1]), "+f"(c[2]), "+f"(c[3])
                 : "r"(a[0]), "r"(a[1]), "r"(a[2]), "r"(a[3]), "r"(b0), "r"(b1));
}
__device__ __forceinline__ void split_hilo_h(float v, __half& h, __half& l) {
    h = __float2half(v);
    l = __float2half(v - __half2float(h));
}

// ---------------- fp32 -> fp16 hi/lo split ----------------
__global__ void cvt_hilo_kernel(const float* __restrict__ x,
                                __half* __restrict__ hi,
                                __half* __restrict__ lo, size_t n) {
    size_t i = (size_t)blockIdx.x * blockDim.x + threadIdx.x;
    if (i >= n) return;
    __half h, lv;
    split_hilo_h(x[i], h, lv);
    hi[i] = h; lo[i] = lv;
}
__global__ void cvt_h_kernel(const float* __restrict__ x, __half* __restrict__ o, size_t n) {
    size_t i = (size_t)blockIdx.x * blockDim.x + threadIdx.x;
    if (i >= n) return;
    o[i] = __float2half(x[i]);
}

// ===== mma.sync fp16 2-term GEMM, 3-stage cp.async pipeline =====
#define KC 32
#define APAD 40

__global__ __launch_bounds__(256, 2) void gemm_2t(
    const __half* __restrict__ Ah, const __half* __restrict__ Al,
    const __half* __restrict__ Bw,
    float* __restrict__ Cc, int Ntot, int Ktot) {
    extern __shared__ __align__(16) __half sm[];
    const int tid = threadIdx.x;
    const int bRow = blockIdx.y * 128, bCol = blockIdx.x * 128;
    const int wid = tid >> 5, lane = tid & 31;
    const int wm = (wid >> 2) * 64, wn = (wid & 3) * 32;

    __half* sp[3][3];
#pragma unroll
    for (int s = 0; s < 3; s++)
#pragma unroll
        for (int o = 0; o < 3; o++) sp[s][o] = sm + ((s * 3 + o) * 128 * APAD);

    float acc[4][4][4];
#pragma unroll
    for (int i = 0; i < 4; i++)
#pragma unroll
        for (int j = 0; j < 4; j++)
#pragma unroll
            for (int q = 0; q < 4; q++) acc[i][j][q] = 0.f;

    const int nst = Ktot / KC;

    auto issue = [&](int s, int c) {
        int kt = c * KC;
#pragma unroll
        for (int i = 0; i < 2; i++) {
            int u = tid + i * 256;
            int r = u >> 2, kc = (u & 3) * 8;
            size_t ga = (size_t)(bRow + r) * Ktot + kt + kc;
            cp_async16(smem_u32(sp[s][0] + r * APAD + kc), Ah + ga, 16);
            cp_async16(smem_u32(sp[s][1] + r * APAD + kc), Al + ga, 16);
            int ok = (bCol + r) < Ntot ? 16 : 0;
            size_t gb = ok ? ((size_t)(bCol + r) * Ktot + kt + kc) : 0;
            cp_async16(smem_u32(sp[s][2] + r * APAD + kc), Bw + gb, ok);
        }
    };

    issue(0, 0);
    CP_COMMIT();
    if (nst > 1) { issue(1, 1); CP_COMMIT(); }

    const int ar = lane & 15, ac = (lane >> 4) * 8;
    int st3 = 0;
    for (int c = 0; c < nst; c++) {
        if (c + 2 < nst) {
            int s2 = st3 + 2; if (s2 >= 3) s2 -= 3;
            issue(s2, c + 2); CP_COMMIT(); CP_WAIT2();
        } else if (c + 1 < nst) CP_WAIT1();
        else CP_WAIT0();
        __syncthreads();
        const __half* sa_h = sp[st3][0];
        const __half* sa_l = sp[st3][1];
        const __half* sb   = sp[st3][2];
#pragma unroll
        for (int kk = 0; kk < 2; kk++) {
            int k0 = kk * 16;
            uint32_t bf[2][4];
#pragma unroll
            for (int bt = 0; bt < 2; bt++)
                ldsm4(bf[bt], smem_u32(sb + (wn + bt * 16 + ar) * APAD + k0 + ac));
#pragma unroll
            for (int mt = 0; mt < 4; mt++) {
                uint32_t afh[4], afl[4];
                ldsm4(afh, smem_u32(sa_h + (wm + mt * 16 + ar) * APAD + k0 + ac));
                ldsm4(afl, smem_u32(sa_l + (wm + mt * 16 + ar) * APAD + k0 + ac));
#pragma unroll
                for (int nt = 0; nt < 4; nt++) {
                    int bt = nt >> 1, sel = nt & 1;
                    mma16816h(acc[mt][nt], afh, bf[bt][sel], bf[bt][sel + 2]);
                }
#pragma unroll
                for (int nt = 0; nt < 4; nt++) {
                    int bt = nt >> 1, sel = nt & 1;
                    mma16816h(acc[mt][nt], afl, bf[bt][sel], bf[bt][sel + 2]);
                }
            }
        }
        __syncthreads();
        if (++st3 == 3) st3 = 0;
    }

    const int g = lane >> 2, t4 = lane & 3;
#pragma unroll
    for (int mt = 0; mt < 4; mt++) {
#pragma unroll
        for (int nt = 0; nt < 4; nt++) {
            int row = bRow + wm + mt * 16 + g;
            int col = bCol + wn + nt * 8 + t4 * 2;
            if (col < Ntot) {
                float* p0 = Cc + (size_t)row * Ntot + col;
                p0[0] = acc[mt][nt][0];
                p0[1] = acc[mt][nt][1];
                float* p1 = p0 + (size_t)8 * Ntot;
                p1[0] = acc[mt][nt][2];
                p1[1] = acc[mt][nt][3];
            }
        }
    }
}

// ---------------- generic NT SGEMM (small batched G = C B^T) --------
__global__ __launch_bounds__(256) void sgemm_nt(const float* __restrict__ A,
                                                const float* __restrict__ B,
                                                float* __restrict__ C,
                                                int M, int N, int K,
                                                long sA, long sB, long sC) {
    A += (size_t)blockIdx.z * sA;
    B += (size_t)blockIdx.z * sB;
    C += (size_t)blockIdx.z * sC;
    __shared__ float As[16][128];
    __shared__ float Bs[16][128];
    int tid = threadIdx.x;
    int bRow = blockIdx.y * 128, bCol = blockIdx.x * 128;
    int tx = tid & 15, ty = tid >> 4;
    float acc[8][8] = {};
    int lr = tid >> 2;
    int lk = (tid & 3) * 4;
    for (int kt = 0; kt < K; kt += 16) {
#pragma unroll
        for (int p = 0; p < 2; p++) {
            int r = lr + p * 64;
            int row = bRow + r;
            float4 v = make_float4(0.f, 0.f, 0.f, 0.f);
            if (row < M) v = *(const float4*)(A + (size_t)row * K + kt + lk);
            As[lk][r] = v.x; As[lk + 1][r] = v.y; As[lk + 2][r] = v.z; As[lk + 3][r] = v.w;
            int col = bCol + r;
            float4 w = make_float4(0.f, 0.f, 0.f, 0.f);
            if (col < N) w = *(const float4*)(B + (size_t)col * K + kt + lk);
            Bs[lk][r] = w.x; Bs[lk + 1][r] = w.y; Bs[lk + 2][r] = w.z; Bs[lk + 3][r] = w.w;
        }
        __syncthreads();
#pragma unroll
        for (int k = 0; k < 16; k++) {
            float ra[8], rb[8];
            *(float4*)ra       = *(const float4*)&As[k][ty * 8];
            *(float4*)(ra + 4) = *(const float4*)&As[k][ty * 8 + 4];
            *(float4*)rb       = *(const float4*)&Bs[k][tx * 8];
            *(float4*)(rb + 4) = *(const float4*)&Bs[k][tx * 8 + 4];
#pragma unroll
            for (int i = 0; i < 8; i++)
#pragma unroll
                for (int j = 0; j < 8; j++)
                    acc[i][j] += ra[i] * rb[j];
        }
        __syncthreads();
    }
    for (int i = 0; i < 8; i++) {
        int row = bRow + ty * 8 + i;
        if (row >= M) continue;
        for (int j = 0; j < 8; j++) {
            int col = bCol + tx * 8 + j;
            if (col < N) C[(size_t)row * N + col] = acc[i][j];
        }
    }
}

// ---------------- depthwise causal conv (k=4) + bias + silu ----------------
__global__ void conv_kernel(const float* __restrict__ cw, const float* __restrict__ cb) {
    size_t idx = (size_t)blockIdx.x * blockDim.x + threadIdx.x;
    if (idx >= (size_t)L * CONVD) return;
    int c = (int)(idx % CONVD);
    int t = (int)(idx / CONVD);
    float acc = cb[c];
#pragma unroll
    for (int k = 0; k < 4; k++) {
        int ts = t - 3 + k;
        if (ts >= 0) acc += cw[c * 4 + k] * g_zx[(size_t)ts * DPROJ + DIN + c];
    }
    g_xc[idx] = acc * sigmoidf_(acc);
}

// ---------------- dt (with direction flip) + softplus ----------------
__global__ void dt_kernel(const float* __restrict__ dt_bias) {
    int idx = blockIdx.x * blockDim.x + threadIdx.x;
    if (idx >= 2 * L * NH) return;
    int h = idx & 31;
    int t = (idx >> 5) & (L - 1);
    int dir = idx >> 17;
    int ts = dir ? (L - 1 - t) : t;
    float v = g_zx[(size_t)ts * DPROJ + DIN + CONVD + dir * NH + h] + dt_bias[h];
    g_dt2[idx] = (v > 20.f) ? v : log1pf(expf(v));
}

// ---------------- B/C split per direction (flip for dir1) ----------------
__global__ void prep_bc_kernel() {
    int idx = blockIdx.x * blockDim.x + threadIdx.x;
    if (idx >= 2 * L * NST) return;
    int n = idx & 127;
    int t = (idx >> 7) & (L - 1);
    int dir = idx >> 19;
    int ts = dir ? (L - 1 - t) : t;
    int off = dir ? 256 : 0;
    const float* p = g_xc + (size_t)ts * CONVD + DIN + off;
    g_Bm[idx] = p[n];
    g_Cm[idx] = p[NST + n];
}

// ---------------- per-chunk cumsum of A*dt ----------------
__global__ void acs_kernel(const float* __restrict__ A_log) {
    int c = blockIdx.x, dir = blockIdx.y, h = threadIdx.x;
    float Ah = -expf(A_log[h]);
    float cum = 0.f;
    float* out = g_Acs + (((dir * NC + c) * NH + h) << 7);
    const float* dtp = g_dt2 + ((size_t)(dir * L + c * CHK)) * NH + h;
    for (int l = 0; l < CHK; l++) {
        cum += Ah * dtp[l * NH];
        out[l] = cum;
    }
}

// ---------------- per (dir,chunk,head): Y_diag = (G.*Lmat)@xdt ; states = B^T @ (decay.*xdt) ----
// decay mask via factored __expf: exp(Acs[l]-Acs[s]) = exp(Acs[l]-m_tile) * exp(m_tile-Acs[s])
__global__ __launch_bounds__(256) void ydiag_states_kernel() {
    int b = blockIdx.x;
    int h = b & 31, c = (b >> 5) & 31, dir = b >> 10;
    int tid = threadIdx.x;
    __shared__ float sAcs[CHK];
    __shared__ float sDt[CHK];
    __shared__ float sCv[CHK];       // col factors exp(m_tile - Acs[s])
    __shared__ float sR[CHK][8];     // row factors exp(Acs[l] - m_tile[st]) (clamped)
    __shared__ float sMl[CHK][17];
    __shared__ float sXs[16][68];
    __shared__ float sB[16][132];
    __shared__ float sXd[16][68];
    if (tid < CHK) {
        sAcs[tid] = g_Acs[(b << 7) + tid];
        sDt[tid] = g_dt2[((size_t)(dir * L + c * CHK + tid)) * NH + h];
    }
    __syncthreads();
    if (tid < CHK) sCv[tid] = __expf(sAcs[tid | 15] - sAcs[tid]);
    {
        // 1024 entries: idx = l*8 + st
        int i0 = tid * 4;
#pragma unroll
        for (int q = 0; q < 4; q++) {
            int idx = i0 + q;
            int l = idx >> 3, st = idx & 7;
            sR[l][st] = __expf(fminf(sAcs[l] - sAcs[st * 16 + 15], 85.f));
        }
    }
    __syncthreads();
    const float* Gp = g_G + ((size_t)(dir * NC + c) << 14);
    int tx = tid & 15, ty = tid >> 4;
    float acc[8][4] = {};
    int l0 = tid >> 1, skb = (tid & 1) * 8;
    for (int st = 0; st < 8; st++) {
        {
            float r = sR[l0][st];
#pragma unroll
            for (int i = 0; i < 8; i++) {
                int s = st * 16 + skb + i;
                float g = Gp[l0 * CHK + s];
                sMl[l0][skb + i] = (l0 >= s) ? g * r * sCv[s] : 0.f;
            }
        }
        {
            int sk = tid >> 4, p0 = (tid & 15) * 4;
            int l = st * 16 + sk;
            int tg = c * CHK + l;
            int ts = dir ? (L - 1 - tg) : tg;
            float dtv = sDt[l];
            float4 v = *(const float4*)(g_xc + (size_t)ts * CONVD + h * HD + p0);
            sXs[sk][p0] = v.x * dtv; sXs[sk][p0 + 1] = v.y * dtv;
            sXs[sk][p0 + 2] = v.z * dtv; sXs[sk][p0 + 3] = v.w * dtv;
        }
        __syncthreads();
#pragma unroll
        for (int sk = 0; sk < 16; sk++) {
            float xb0 = sXs[sk][tx * 4], xb1 = sXs[sk][tx * 4 + 1];
            float xb2 = sXs[sk][tx * 4 + 2], xb3 = sXs[sk][tx * 4 + 3];
#pragma unroll
            for (int i = 0; i < 8; i++) {
                float m = sMl[ty * 8 + i][sk];
                acc[i][0] += m * xb0; acc[i][1] += m * xb1;
                acc[i][2] += m * xb2; acc[i][3] += m * xb3;
            }
        }
        __syncthreads();
    }
    float* Yp = g_Yd + ((size_t)(dir * L + c * CHK)) * DIN + h * HD;
#pragma unroll
    for (int i = 0; i < 8; i++)
#pragma unroll
        for (int j = 0; j < 4; j++)
            Yp[(size_t)(ty * 8 + i) * DIN + tx * 4 + j] = acc[i][j];

    // ---- states ----
    float accS[8][4] = {};
    int n0 = (tid & 31) * 4;
    int p0s = (tid >> 5) * 8;
    float lastA = sAcs[127];
    const float* Bp = g_Bm + ((size_t)(dir * L + c * CHK)) * NST;
    for (int lt = 0; lt < 8; lt++) {
        {
            int lk = tid >> 4, nb = (tid & 15) * 8;
            float4 v0 = *(const float4*)(Bp + (size_t)(lt * 16 + lk) * NST + nb);
            float4 v1 = *(const float4*)(Bp + (size_t)(lt * 16 + lk) * NST + nb + 4);
            sB[lk][nb] = v0.x; sB[lk][nb + 1] = v0.y; sB[lk][nb + 2] = v0.z; sB[lk][nb + 3] = v0.w;
            sB[lk][nb + 4] = v1.x; sB[lk][nb + 5] = v1.y; sB[lk][nb + 6] = v1.z; sB[lk][nb + 7] = v1.w;
            int pb = (tid & 15) * 4;
            int l = lt * 16 + lk;
            int tg = c * CHK + l;
            int ts = dir ? (L - 1 - tg) : tg;
            float dec = __expf(lastA - sAcs[l]) * sDt[l];
            float4 xv = *(const float4*)(g_xc + (size_t)ts * CONVD + h * HD + pb);
            sXd[lk][pb] = xv.x * dec; sXd[lk][pb + 1] = xv.y * dec;
            sXd[lk][pb + 2] = xv.z * dec; sXd[lk][pb + 3] = xv.w * dec;
        }
        __syncthreads();
#pragma unroll
        for (int lk2 = 0; lk2 < 16; lk2++) {
            float pv[8];
#pragma unroll
            for (int i = 0; i < 8; i++) pv[i] = sXd[lk2][p0s + i];
            float nv0 = sB[lk2][n0], nv1 = sB[lk2][n0 + 1];
            float nv2 = sB[lk2][n0 + 2], nv3 = sB[lk2][n0 + 3];
#pragma unroll
            for (int i = 0; i < 8; i++) {
                accS[i][0] += pv[i] * nv0; accS[i][1] += pv[i] * nv1;
                accS[i][2] += pv[i] * nv2; accS[i][3] += pv[i] * nv3;
            }
        }
        __syncthreads();
    }
    float* Sp = g_states + ((size_t)b << 13);
#pragma unroll
    for (int i = 0; i < 8; i++)
#pragma unroll
        for (int j = 0; j < 4; j++)
            Sp[(size_t)(p0s + i) * NST + n0 + j] = accS[i][j];
}

// ---------------- inter-chunk recurrence (8-way split per (dir,h)) ----------------
__global__ void recur_kernel() {
    int bi = blockIdx.x;
    int seg = bi & 7, hh = bi >> 3;
    int dir = hh >> 5, h = hh & 31;
    int tid = threadIdx.x;
    float Hreg[4] = {0.f, 0.f, 0.f, 0.f};
    for (int c = 0; c < NC; c++) {
        int sb = (dir * NC + c) * NH + h;
        float dec = __expf(g_Acs[(sb << 7) + 127]);
        size_t base = ((size_t)sb << 13) + seg * 1024;
#pragma unroll
        for (int k = 0; k < 4; k++) {
            size_t off = base + tid + k * 256;
            float s = g_states[off];
            g_states[off] = Hreg[k];
            Hreg[k] = dec * Hreg[k] + s;
        }
    }
}

// ---------------- Y_off = exp(Acs[l]) * C @ state^T ; Yd += Y_off + x*D ----------------
__global__ __launch_bounds__(256) void yoff_kernel(const float* __restrict__ Dv) {
    int b = blockIdx.x;
    int h = b & 31, c = (b >> 5) & 31, dir = b >> 10;
    int tid = threadIdx.x;
    __shared__ float sAcs[CHK];
    __shared__ float sC[CHK][17];
    __shared__ float sS[64][17];
    if (tid < CHK) sAcs[tid] = g_Acs[(b << 7) + tid];
    __syncthreads();
    const float* Cp = g_Cm + ((size_t)(dir * L + c * CHK)) * NST;
    const float* Sp = g_states + ((size_t)b << 13);
    int tx = tid & 15, ty = tid >> 4;
    float acc[8][4] = {};
    int l0 = tid >> 1, nkb = (tid & 1) * 8;
    int p1 = tid >> 2, nkb2 = (tid & 3) * 4;
    for (int nt = 0; nt < 8; nt++) {
#pragma unroll
        for (int i = 0; i < 8; i++)
            sC[l0][nkb + i] = Cp[(size_t)l0 * NST + nt * 16 + nkb + i];
        {
            float4 v = *(const float4*)(Sp + (size_t)p1 * NST + nt * 16 + nkb2);
            sS[p1][nkb2] = v.x; sS[p1][nkb2 + 1] = v.y;
            sS[p1][nkb2 + 2] = v.z; sS[p1][nkb2 + 3] = v.w;
        }
        __syncthreads();
#pragma unroll
        for (int nk = 0; nk < 16; nk++) {
            float sv0 = sS[tx * 4][nk], sv1 = sS[tx * 4 + 1][nk];
            float sv2 = sS[tx * 4 + 2][nk], sv3 = sS[tx * 4 + 3][nk];
#pragma unroll
            for (int i = 0; i < 8; i++) {
                float cv = sC[ty * 8 + i][nk];
                acc[i][0] += cv * sv0; acc[i][1] += cv * sv1;
                acc[i][2] += cv * sv2; acc[i][3] += cv * sv3;
            }
        }
        __syncthreads();
    }
    float Dh = Dv[h];
    float* Yp = g_Yd + ((size_t)(dir * L + c * CHK)) * DIN + h * HD;
#pragma unroll
    for (int i = 0; i < 8; i++) {
        int l = ty * 8 + i;
        float e = __expf(sAcs[l]);
        int tglob = c * CHK + l;
        int ts = dir ? (L - 1 - tglob) : tglob;
        const float* xrow = g_xc + (size_t)ts * CONVD + h * HD;
#pragma unroll
        for (int j = 0; j < 4; j++) {
            int p = tx * 4 + j;
            size_t o = (size_t)l * DIN + p;
            Yp[o] = Yp[o] + e * acc[i][j] + xrow[p] * Dh;
        }
    }
}

// ---------------- fd = x_og @ fc_D_w^T + D, tiled (32 t-rows per block) ----------------
__global__ __launch_bounds__(256) void fcD_kernel(const float* __restrict__ W,
                                                  const float* __restrict__ Dv) {
    int t0 = blockIdx.x * 32;
    __shared__ float sx[32][132];
    __shared__ float sW[32][132];
    int tid = threadIdx.x;
    int tx = tid & 15, ty = tid >> 4;
    float acc[2][2] = {};
    for (int kc = 0; kc < DIN; kc += 128) {
#pragma unroll
        for (int i = 0; i < 4; i++) {
            int u = tid + i * 256;
            int r = u >> 5, k4 = (u & 31) * 4;
            *(float4*)&sx[r][k4] = *(const float4*)(g_xc + (size_t)(t0 + r) * CONVD + kc + k4);
            *(float4*)&sW[r][k4] = *(const float4*)(W + (size_t)r * DIN + kc + k4);
        }
        __syncthreads();
#pragma unroll 8
        for (int k4 = 0; k4 < 128; k4 += 4) {
            float4 x0 = *(float4*)&sx[ty * 2][k4];
            float4 x1 = *(float4*)&sx[ty * 2 + 1][k4];
            float4 w0 = *(float4*)&sW[tx * 2][k4];
            float4 w1 = *(float4*)&sW[tx * 2 + 1][k4];
            acc[0][0] += x0.x * w0.x + x0.y * w0.y + x0.z * w0.z + x0.w * w0.w;
            acc[0][1] += x0.x * w1.x + x0.y * w1.y + x0.z * w1.z + x0.w * w1.w;
            acc[1][0] += x1.x * w0.x + x1.y * w0.y + x1.z * w0.z + x1.w * w0.w;
            acc[1][1] += x1.x * w1.x + x1.y * w1.y + x1.z * w1.z + x1.w * w1.w;
        }
        __syncthreads();
    }
#pragma unroll
    for (int i = 0; i < 2; i++)
#pragma unroll
        for (int j = 0; j < 2; j++)
            g_fd[(t0 + ty * 2 + i) * NH + tx * 2 + j] = acc[i][j] + Dv[tx * 2 + j];
}

// ---------------- shift + merge dirs + skip + gate + RMSNorm -> fp16 hi/lo ----------------
__global__ void combine_kernel(const float* __restrict__ norm_w) {
    int t = blockIdx.x;
    int tid = threadIdx.x;
    __shared__ float red[256];
    __shared__ float sc;
    float yg[8];
    float ss = 0.f;
#pragma unroll
    for (int k = 0; k < 8; k++) {
        int d = tid + k * 256;
        float yfw = (t > 0) ? g_Yd[((size_t)(t - 1)) * DIN + d] : 0.f;
        float ybw = (t < L - 1) ? g_Yd[((size_t)(L + (L - 2 - t))) * DIN + d] : 0.f;
        float x = g_xc[(size_t)t * CONVD + d];
        float fdv = g_fd[t * NH + (d >> 6)];
        float z = g_zx[(size_t)t * DPROJ + d];
        float v = (yfw + ybw + x * fdv) * (z * sigmoidf_(z));
        yg[k] = v;
        ss += v * v;
    }
    red[tid] = ss;
    __syncthreads();
    for (int o = 128; o > 0; o >>= 1) {
        if (tid < o) red[tid] += red[tid + o];
        __syncthreads();
    }
    if (tid == 0) sc = rsqrtf(red[0] * (1.f / DIN) + EPSV);
    __syncthreads();
    float s = sc;
#pragma unroll
    for (int k = 0; k < 8; k++) {
        int d = tid + k * 256;
        float v = yg[k] * s * norm_w[d];
        __half hv, lv;
        split_hilo_h(v, hv, lv);
        g_ynh[(size_t)t * DIN + d] = hv;
        g_ynl[(size_t)t * DIN + d] = lv;
    }
}

extern "C" void kernel_launch(void* const* d_in, const int* in_sizes, int n_in,
                              void* d_out, int out_size) {
    const float* u          = (const float*)d_in[0];
    const float* in_proj_w  = (const float*)d_in[1];
    const float* conv_w     = (const float*)d_in[2];
    const float* conv_b     = (const float*)d_in[3];
    const float* dt_bias    = (const float*)d_in[4];
    const float* A_log      = (const float*)d_in[5];
    const float* Dv         = (const float*)d_in[6];
    const float* fc_D_w     = (const float*)d_in[7];
    const float* norm_w     = (const float*)d_in[8];
    const float* out_proj_w = (const float*)d_in[9];
    float* out = (float*)d_out;

    float *zx, *Bm, *Cm, *G;
    __half *uh, *ul, *wi, *ynh, *ynl, *wo;
    cudaGetSymbolAddress((void**)&zx, g_zx);
    cudaGetSymbolAddress((void**)&Bm, g_Bm);
    cudaGetSymbolAddress((void**)&Cm, g_Cm);
    cudaGetSymbolAddress((void**)&G, g_G);
    cudaGetSymbolAddress((void**)&uh, g_uh);
    cudaGetSymbolAddress((void**)&ul, g_ul);
    cudaGetSymbolAddress((void**)&wi, g_wi);
    cudaGetSymbolAddress((void**)&ynh, g_ynh);
    cudaGetSymbolAddress((void**)&ynl, g_ynl);
    cudaGetSymbolAddress((void**)&wo, g_wo);

    const int smemB = 3 * 3 * 128 * APAD * 2;  // 92160 B
    cudaFuncSetAttribute(gemm_2t, cudaFuncAttributeMaxDynamicSharedMemorySize, smemB);

    // 0) convert: activations fp16 hi/lo, weights single fp16
    cvt_hilo_kernel<<<((size_t)L * DM + 255) / 256, 256>>>(u, uh, ul, (size_t)L * DM);
    cvt_h_kernel<<<((size_t)DPROJ * DM + 255) / 256, 256>>>(in_proj_w, wi, (size_t)DPROJ * DM);
    cvt_h_kernel<<<((size_t)DM * DIN + 255) / 256, 256>>>(out_proj_w, wo, (size_t)DM * DIN);

    // 1) in_proj
    gemm_2t<<<dim3((DPROJ + 127) / 128, L / 128), 256, smemB>>>(uh, ul, wi, zx, DPROJ, DM);
    // 2) conv + silu
    conv_kernel<<<((size_t)L * CONVD + 255) / 256, 256>>>(conv_w, conv_b);
    // 3) dt softplus
    dt_kernel<<<(2 * L * NH + 255) / 256, 256>>>(dt_bias);
    // 4) B/C prep
    prep_bc_kernel<<<(2 * L * NST + 255) / 256, 256>>>();
    // 5) per-chunk cumsum of A*dt
    acs_kernel<<<dim3(NC, 2), 32>>>(A_log);
    // 6) G = C B^T per (dir,chunk)
    sgemm_nt<<<dim3(1, 1, 2 * NC), 256>>>(Cm, Bm, G, CHK, CHK, NST,
                                          CHK * NST, CHK * NST, CHK * CHK);
    // 7) Y_diag + chunk states (factored-exp decay mask)
    ydiag_states_kernel<<<2 * NC * NH, 256>>>();
    // 8) inter-chunk recurrence
    recur_kernel<<<512, 256>>>();
    // 9) Y_off + x*D
    yoff_kernel<<<2 * NC * NH, 256>>>(Dv);
    // 10) fd
    fcD_kernel<<<L / 32, 256>>>(fc_D_w, Dv);
    // 11) shift/merge/gate/RMSNorm
    combine_kernel<<<L, 256>>>(norm_w);
    // 12) out_proj
    gemm_2t<<<dim3(DM / 128, L / 128), 256, smemB>>>(ynh, ynl, wo, out, DM, DIN);
}

// round 10
// speedup vs baseline: 1.5942x; 1.0548x over previous
#include <cuda_runtime.h>
#include <cuda_bf16.h>
#include <cuda_fp16.h>
#include <math.h>
#include <stdint.h>

#define L 4096
#define DM 1024
#define DIN 2048
#define NH 32
#define HD 64
#define NST 128
#define CONVD 2560
#define DPROJ 4672
#define CHK 128
#define NC 32
#define EPSV 1e-5f

// ---------------- scratch (static device globals; no allocation) ----------------
__device__ float g_zx[(size_t)L * DPROJ];
__device__ float g_xc[(size_t)L * CONVD];
__device__ float g_dt2[2 * L * NH];
__device__ float g_Bm[(size_t)2 * L * NST];
__device__ float g_Cm[(size_t)2 * L * NST];
__device__ float g_Acs[2 * NC * NH * CHK];
__device__ float g_G[(size_t)2 * NC * CHK * CHK];
__device__ float g_Yd[(size_t)2 * L * DIN];
__device__ float g_states[(size_t)2 * NC * NH * HD * NST];
__device__ float g_fd[L * NH];

__device__ __align__(16) __half g_uh[(size_t)L * DM];
__device__ __align__(16) __half g_ul[(size_t)L * DM];
__device__ __align__(16) __half g_wi[(size_t)DPROJ * DM];
__device__ __align__(16) __half g_ynh[(size_t)L * DIN];
__device__ __align__(16) __half g_ynl[(size_t)L * DIN];
__device__ __align__(16) __half g_wo[(size_t)DM * DIN];

__device__ __forceinline__ float sigmoidf_(float x) { return 1.f / (1.f + __expf(-x)); }

__device__ __forceinline__ uint32_t smem_u32(const void* p) {
    uint32_t a;
    asm("{ .reg .u64 tmp; cvta.to.shared.u64 tmp, %1; cvt.u32.u64 %0, tmp; }" : "=r"(a) : "l"(p));
    return a;
}
__device__ __forceinline__ void cp_async16(uint32_t dst, const void* src, int srcsize) {
    asm volatile("cp.async.cg.shared.global [%0], [%1], 16, %2;"
                 :: "r"(dst), "l"(src), "r"(srcsize));
}
#define CP_COMMIT() asm volatile("cp.async.commit_group;" ::: "memory")
#define CP_WAIT1()  asm volatile("cp.async.wait_group 1;"  ::: "memory")
#define CP_WAIT0()  asm volatile("cp.async.wait_group 0;"  ::: "memory")

__device__ __forceinline__ void ldsm4(uint32_t* r, uint32_t addr) {
    asm volatile("ldmatrix.sync.aligned.m8n8.x4.shared.b16 {%0,%1,%2,%3}, [%4];"
                 : "=r"(r[0]), "=r"(r[1]), "=r"(r[2]), "=r"(r[3]) : "r"(addr));
}
__device__ __forceinline__ void mma16816h(float* c, const uint32_t* a, uint32_t b0, uint32_t b1) {
    asm volatile("mma.sync.aligned.m16n8k16.row.col.f32.f16.f16.f32 "
                 "{%0,%1,%2,%3}, {%4,%5,%6,%7}, {%8,%9}, {%0,%1,%2,%3};"
                 : "+f"(c[0]), "+f"(c[1]), "+f"(c[2]), "+f"(c[3])
                 : "r"(a[0]), "r"(a[1]), "r"(a[2]), "r"(a[3]), "r"(b0), "r"(b1));
}
__device__ __forceinline__ void split_hilo_h(float v, __half& h, __half& l) {
    h = __float2half(v);
    l = __float2half(v - __half2float(h));
}

// ---------------- fp32 -> fp16 hi/lo split ----------------
__global__ void cvt_hilo_kernel(const float* __restrict__ x,
                                __half* __restrict__ hi,
                                __half* __restrict__ lo, size_t n) {
    size_t i = (size_t)blockIdx.x * blockDim.x + threadIdx.x;
    if (i >= n) return;
    __half h, lv;
    split_hilo_h(x[i], h, lv);
    hi[i] = h; lo[i] = lv;
}
__global__ void cvt_h_kernel(const float* __restrict__ x, __half* __restrict__ o, size_t n) {
    size_t i = (size_t)blockIdx.x * blockDim.x + threadIdx.x;
    if (i >= n) return;
    o[i] = __float2half(x[i]);
}

// ===== mma.sync fp16 2-term GEMM, 2-stage cp.async pipeline (R7-proven) =====
#define KC 32
#define APAD 40

__global__ __launch_bounds__(256, 2) void gemm_2t(
    const __half* __restrict__ Ah, const __half* __restrict__ Al,
    const __half* __restrict__ Bw,
    float* __restrict__ Cc, int Ntot, int Ktot) {
    extern __shared__ __align__(16) __half sm[];
    const int tid = threadIdx.x;
    const int bRow = blockIdx.y * 128, bCol = blockIdx.x * 128;
    const int wid = tid >> 5, lane = tid & 31;
    const int wm = (wid >> 2) * 64, wn = (wid & 3) * 32;

    __half* sp[2][3];
#pragma unroll
    for (int s = 0; s < 2; s++)
#pragma unroll
        for (int o = 0; o < 3; o++) sp[s][o] = sm + ((s * 3 + o) * 128 * APAD);

    float acc[4][4][4];
#pragma unroll
    for (int i = 0; i < 4; i++)
#pragma unroll
        for (int j = 0; j < 4; j++)
#pragma unroll
            for (int q = 0; q < 4; q++) acc[i][j][q] = 0.f;

    const int nst = Ktot / KC;

    auto issue = [&](int s, int c) {
        int kt = c * KC;
#pragma unroll
        for (int i = 0; i < 2; i++) {
            int u = tid + i * 256;
            int r = u >> 2, kc = (u & 3) * 8;
            size_t ga = (size_t)(bRow + r) * Ktot + kt + kc;
            cp_async16(smem_u32(sp[s][0] + r * APAD + kc), Ah + ga, 16);
            cp_async16(smem_u32(sp[s][1] + r * APAD + kc), Al + ga, 16);
            int ok = (bCol + r) < Ntot ? 16 : 0;
            size_t gb = ok ? ((size_t)(bCol + r) * Ktot + kt + kc) : 0;
            cp_async16(smem_u32(sp[s][2] + r * APAD + kc), Bw + gb, ok);
        }
    };

    issue(0, 0);
    CP_COMMIT();

    const int ar = lane & 15, ac = (lane >> 4) * 8;
    for (int c = 0; c < nst; c++) {
        if (c + 1 < nst) { issue((c + 1) & 1, c + 1); CP_COMMIT(); CP_WAIT1(); }
        else CP_WAIT0();
        __syncthreads();
        const __half* sa_h = sp[c & 1][0];
        const __half* sa_l = sp[c & 1][1];
        const __half* sb   = sp[c & 1][2];
#pragma unroll
        for (int kk = 0; kk < 2; kk++) {
            int k0 = kk * 16;
            uint32_t bf[2][4];
#pragma unroll
            for (int bt = 0; bt < 2; bt++)
                ldsm4(bf[bt], smem_u32(sb + (wn + bt * 16 + ar) * APAD + k0 + ac));
#pragma unroll
            for (int mt = 0; mt < 4; mt++) {
                uint32_t afh[4], afl[4];
                ldsm4(afh, smem_u32(sa_h + (wm + mt * 16 + ar) * APAD + k0 + ac));
                ldsm4(afl, smem_u32(sa_l + (wm + mt * 16 + ar) * APAD + k0 + ac));
#pragma unroll
                for (int nt = 0; nt < 4; nt++) {
                    int bt = nt >> 1, sel = nt & 1;
                    mma16816h(acc[mt][nt], afh, bf[bt][sel], bf[bt][sel + 2]);
                }
#pragma unroll
                for (int nt = 0; nt < 4; nt++) {
                    int bt = nt >> 1, sel = nt & 1;
                    mma16816h(acc[mt][nt], afl, bf[bt][sel], bf[bt][sel + 2]);
                }
            }
        }
        __syncthreads();
    }

    const int g = lane >> 2, t4 = lane & 3;
#pragma unroll
    for (int mt = 0; mt < 4; mt++) {
#pragma unroll
        for (int nt = 0; nt < 4; nt++) {
            int row = bRow + wm + mt * 16 + g;
            int col = bCol + wn + nt * 8 + t4 * 2;
            if (col < Ntot) {
                float* p0 = Cc + (size_t)row * Ntot + col;
                p0[0] = acc[mt][nt][0];
                p0[1] = acc[mt][nt][1];
                float* p1 = p0 + (size_t)8 * Ntot;
                p1[0] = acc[mt][nt][2];
                p1[1] = acc[mt][nt][3];
            }
        }
    }
}

// ---------------- 64x64-tile batched NT SGEMM for G = C B^T (full-chip grid) --------
__global__ __launch_bounds__(256) void sgemm64_nt(const float* __restrict__ A,
                                                  const float* __restrict__ B,
                                                  float* __restrict__ C) {
    // per z-batch: 128x128 output, K = NST = 128. Tiles 64x64, grid (2,2,64)
    A += (size_t)blockIdx.z * CHK * NST;
    B += (size_t)blockIdx.z * CHK * NST;
    C += (size_t)blockIdx.z * CHK * CHK;
    __shared__ float As[16][68];
    __shared__ float Bs[16][68];
    int tid = threadIdx.x;
    int bRow = blockIdx.y * 64, bCol = blockIdx.x * 64;
    int tx = tid & 15, ty = tid >> 4;
    float acc[4][4] = {};
    int lr = tid >> 2, lk = (tid & 3) * 4;
    for (int kt = 0; kt < NST; kt += 16) {
        {
            float4 v = *(const float4*)(A + (size_t)(bRow + lr) * NST + kt + lk);
            As[lk][lr] = v.x; As[lk + 1][lr] = v.y; As[lk + 2][lr] = v.z; As[lk + 3][lr] = v.w;
            float4 w = *(const float4*)(B + (size_t)(bCol + lr) * NST + kt + lk);
            Bs[lk][lr] = w.x; Bs[lk + 1][lr] = w.y; Bs[lk + 2][lr] = w.z; Bs[lk + 3][lr] = w.w;
        }
        __syncthreads();
#pragma unroll
        for (int k = 0; k < 16; k++) {
            float4 ra = *(const float4*)&As[k][ty * 4];
            float4 rb = *(const float4*)&Bs[k][tx * 4];
            float a0 = ra.x, a1 = ra.y, a2 = ra.z, a3 = ra.w;
            acc[0][0] += a0 * rb.x; acc[0][1] += a0 * rb.y; acc[0][2] += a0 * rb.z; acc[0][3] += a0 * rb.w;
            acc[1][0] += a1 * rb.x; acc[1][1] += a1 * rb.y; acc[1][2] += a1 * rb.z; acc[1][3] += a1 * rb.w;
            acc[2][0] += a2 * rb.x; acc[2][1] += a2 * rb.y; acc[2][2] += a2 * rb.z; acc[2][3] += a2 * rb.w;
            acc[3][0] += a3 * rb.x; acc[3][1] += a3 * rb.y; acc[3][2] += a3 * rb.z; acc[3][3] += a3 * rb.w;
        }
        __syncthreads();
    }
#pragma unroll
    for (int i = 0; i < 4; i++) {
        float* p = C + (size_t)(bRow + ty * 4 + i) * CHK + bCol + tx * 4;
        p[0] = acc[i][0]; p[1] = acc[i][1]; p[2] = acc[i][2]; p[3] = acc[i][3];
    }
}

// ---------------- depthwise causal conv (k=4) + bias + silu ----------------
__global__ void conv_kernel(const float* __restrict__ cw, const float* __restrict__ cb) {
    size_t idx = (size_t)blockIdx.x * blockDim.x + threadIdx.x;
    if (idx >= (size_t)L * CONVD) return;
    int c = (int)(idx % CONVD);
    int t = (int)(idx / CONVD);
    float acc = cb[c];
#pragma unroll
    for (int k = 0; k < 4; k++) {
        int ts = t - 3 + k;
        if (ts >= 0) acc += cw[c * 4 + k] * g_zx[(size_t)ts * DPROJ + DIN + c];
    }
    g_xc[idx] = acc * sigmoidf_(acc);
}

// ---------------- dt (with direction flip) + softplus ----------------
__global__ void dt_kernel(const float* __restrict__ dt_bias) {
    int idx = blockIdx.x * blockDim.x + threadIdx.x;
    if (idx >= 2 * L * NH) return;
    int h = idx & 31;
    int t = (idx >> 5) & (L - 1);
    int dir = idx >> 17;
    int ts = dir ? (L - 1 - t) : t;
    float v = g_zx[(size_t)ts * DPROJ + DIN + CONVD + dir * NH + h] + dt_bias[h];
    g_dt2[idx] = (v > 20.f) ? v : log1pf(expf(v));
}

// ---------------- B/C split per direction (flip for dir1) ----------------
__global__ void prep_bc_kernel() {
    int idx = blockIdx.x * blockDim.x + threadIdx.x;
    if (idx >= 2 * L * NST) return;
    int n = idx & 127;
    int t = (idx >> 7) & (L - 1);
    int dir = idx >> 19;
    int ts = dir ? (L - 1 - t) : t;
    int off = dir ? 256 : 0;
    const float* p = g_xc + (size_t)ts * CONVD + DIN + off;
    g_Bm[idx] = p[n];
    g_Cm[idx] = p[NST + n];
}

// ---------------- per-chunk cumsum of A*dt ----------------
__global__ void acs_kernel(const float* __restrict__ A_log) {
    int c = blockIdx.x, dir = blockIdx.y, h = threadIdx.x;
    float Ah = -expf(A_log[h]);
    float cum = 0.f;
    float* out = g_Acs + (((dir * NC + c) * NH + h) << 7);
    const float* dtp = g_dt2 + ((size_t)(dir * L + c * CHK)) * NH + h;
    for (int l = 0; l < CHK; l++) {
        cum += Ah * dtp[l * NH];
        out[l] = cum;
    }
}

// ---------------- per (dir,chunk,head): Y_diag = (G.*Lmat)@xdt ; states = B^T @ (decay.*xdt) ----
// transposed smem operand layouts -> float4/broadcast LDS in the FMA loops
__global__ __launch_bounds__(256) void ydiag_states_kernel() {
    int b = blockIdx.x;
    int h = b & 31, c = (b >> 5) & 31, dir = b >> 10;
    int tid = threadIdx.x;
    __shared__ float sAcs[CHK];
    __shared__ float sDt[CHK];
    __shared__ float sCv[CHK];
    __shared__ float sR[CHK][8];
    __shared__ __align__(16) float sMlT[16][132];   // [s_in_slab][l]
    __shared__ __align__(16) float sXs[16][68];     // [k][p]
    __shared__ __align__(16) float sB[16][132];     // [k][n]
    __shared__ __align__(16) float sXd[16][68];     // [k][p]
    if (tid < CHK) {
        sAcs[tid] = g_Acs[(b << 7) + tid];
        sDt[tid] = g_dt2[((size_t)(dir * L + c * CHK + tid)) * NH + h];
    }
    __syncthreads();
    if (tid < CHK) sCv[tid] = __expf(sAcs[tid | 15] - sAcs[tid]);
    {
        int i0 = tid * 4;
#pragma unroll
        for (int q = 0; q < 4; q++) {
            int idx = i0 + q;
            int l = idx >> 3, st = idx & 7;
            sR[l][st] = __expf(fminf(sAcs[l] - sAcs[st * 16 + 15], 85.f));
        }
    }
    __syncthreads();
    const float* Gp = g_G + ((size_t)(dir * NC + c) << 14);
    int tx = tid & 15, ty = tid >> 4;
    float acc[8][4] = {};
    int l0 = tid >> 1, skb = (tid & 1) * 8;
    for (int st = 0; st < 8; st++) {
        {
            float r = sR[l0][st];
#pragma unroll
            for (int i = 0; i < 8; i++) {
                int s = st * 16 + skb + i;
                float g = Gp[l0 * CHK + s];
                sMlT[skb + i][l0] = (l0 >= s) ? g * r * sCv[s] : 0.f;
            }
        }
        {
            int sk = tid >> 4, p0 = (tid & 15) * 4;
            int l = st * 16 + sk;
            int tg = c * CHK + l;
            int ts = dir ? (L - 1 - tg) : tg;
            float dtv = sDt[l];
            float4 v = *(const float4*)(g_xc + (size_t)ts * CONVD + h * HD + p0);
            sXs[sk][p0] = v.x * dtv; sXs[sk][p0 + 1] = v.y * dtv;
            sXs[sk][p0 + 2] = v.z * dtv; sXs[sk][p0 + 3] = v.w * dtv;
        }
        __syncthreads();
#pragma unroll
        for (int sk = 0; sk < 16; sk++) {
            float4 xv = *(const float4*)&sXs[sk][tx * 4];
            float4 m0 = *(const float4*)&sMlT[sk][ty * 8];
            float4 m1 = *(const float4*)&sMlT[sk][ty * 8 + 4];
            float mm[8] = {m0.x, m0.y, m0.z, m0.w, m1.x, m1.y, m1.z, m1.w};
#pragma unroll
            for (int i = 0; i < 8; i++) {
                acc[i][0] += mm[i] * xv.x; acc[i][1] += mm[i] * xv.y;
                acc[i][2] += mm[i] * xv.z; acc[i][3] += mm[i] * xv.w;
            }
        }
        __syncthreads();
    }
    float* Yp = g_Yd + ((size_t)(dir * L + c * CHK)) * DIN + h * HD;
#pragma unroll
    for (int i = 0; i < 8; i++)
#pragma unroll
        for (int j = 0; j < 4; j++)
            Yp[(size_t)(ty * 8 + i) * DIN + tx * 4 + j] = acc[i][j];

    // ---- states ----
    float accS[8][4] = {};
    int n0 = (tid & 31) * 4;
    int p0s = (tid >> 5) * 8;
    float lastA = sAcs[127];
    const float* Bp = g_Bm + ((size_t)(dir * L + c * CHK)) * NST;
    for (int lt = 0; lt < 8; lt++) {
        {
            int lk = tid >> 4, nb = (tid & 15) * 8;
            float4 v0 = *(const float4*)(Bp + (size_t)(lt * 16 + lk) * NST + nb);
            float4 v1 = *(const float4*)(Bp + (size_t)(lt * 16 + lk) * NST + nb + 4);
            sB[lk][nb] = v0.x; sB[lk][nb + 1] = v0.y; sB[lk][nb + 2] = v0.z; sB[lk][nb + 3] = v0.w;
            sB[lk][nb + 4] = v1.x; sB[lk][nb + 5] = v1.y; sB[lk][nb + 6] = v1.z; sB[lk][nb + 7] = v1.w;
            int pb = (tid & 15) * 4;
            int l = lt * 16 + lk;
            int tg = c * CHK + l;
            int ts = dir ? (L - 1 - tg) : tg;
            float dec = __expf(lastA - sAcs[l]) * sDt[l];
            float4 xv = *(const float4*)(g_xc + (size_t)ts * CONVD + h * HD + pb);
            sXd[lk][pb] = xv.x * dec; sXd[lk][pb + 1] = xv.y * dec;
            sXd[lk][pb + 2] = xv.z * dec; sXd[lk][pb + 3] = xv.w * dec;
        }
        __syncthreads();
#pragma unroll
        for (int lk2 = 0; lk2 < 16; lk2++) {
            float4 p0v = *(const float4*)&sXd[lk2][p0s];
            float4 p1v = *(const float4*)&sXd[lk2][p0s + 4];
            float pv[8] = {p0v.x, p0v.y, p0v.z, p0v.w, p1v.x, p1v.y, p1v.z, p1v.w};
            float4 nv = *(const float4*)&sB[lk2][n0];
#pragma unroll
            for (int i = 0; i < 8; i++) {
                accS[i][0] += pv[i] * nv.x; accS[i][1] += pv[i] * nv.y;
                accS[i][2] += pv[i] * nv.z; accS[i][3] += pv[i] * nv.w;
            }
        }
        __syncthreads();
    }
    float* Sp = g_states + ((size_t)b << 13);
#pragma unroll
    for (int i = 0; i < 8; i++)
#pragma unroll
        for (int j = 0; j < 4; j++)
            Sp[(size_t)(p0s + i) * NST + n0 + j] = accS[i][j];
}

// ---------------- inter-chunk recurrence (8-way split per (dir,h)) ----------------
__global__ void recur_kernel() {
    int bi = blockIdx.x;
    int seg = bi & 7, hh = bi >> 3;
    int dir = hh >> 5, h = hh & 31;
    int tid = threadIdx.x;
    float Hreg[4] = {0.f, 0.f, 0.f, 0.f};
    for (int c = 0; c < NC; c++) {
        int sb = (dir * NC + c) * NH + h;
        float dec = __expf(g_Acs[(sb << 7) + 127]);
        size_t base = ((size_t)sb << 13) + seg * 1024;
#pragma unroll
        for (int k = 0; k < 4; k++) {
            size_t off = base + tid + k * 256;
            float s = g_states[off];
            g_states[off] = Hreg[k];
            Hreg[k] = dec * Hreg[k] + s;
        }
    }
}

// ---------------- Y_off = exp(Acs[l]) * C @ state^T ; Yd += Y_off + x*D ----------------
// transposed smem layouts for vector LDS
__global__ __launch_bounds__(256) void yoff_kernel(const float* __restrict__ Dv) {
    int b = blockIdx.x;
    int h = b & 31, c = (b >> 5) & 31, dir = b >> 10;
    int tid = threadIdx.x;
    __shared__ float sAcs[CHK];
    __shared__ __align__(16) float sCT[16][132];   // [n_in_slab][l]
    __shared__ __align__(16) float sST[16][68];    // [n_in_slab][p]
    if (tid < CHK) sAcs[tid] = g_Acs[(b << 7) + tid];
    __syncthreads();
    const float* Cp = g_Cm + ((size_t)(dir * L + c * CHK)) * NST;
    const float* Sp = g_states + ((size_t)b << 13);
    int tx = tid & 15, ty = tid >> 4;
    float acc[8][4] = {};
    int l0 = tid >> 1, nkb = (tid & 1) * 8;
    int p1 = tid >> 2, nkb2 = (tid & 3) * 4;
    for (int nt = 0; nt < 8; nt++) {
#pragma unroll
        for (int i = 0; i < 8; i++)
            sCT[nkb + i][l0] = Cp[(size_t)l0 * NST + nt * 16 + nkb + i];
        {
            float4 v = *(const float4*)(Sp + (size_t)p1 * NST + nt * 16 + nkb2);
            sST[nkb2][p1] = v.x; sST[nkb2 + 1][p1] = v.y;
            sST[nkb2 + 2][p1] = v.z; sST[nkb2 + 3][p1] = v.w;
        }
        __syncthreads();
#pragma unroll
        for (int nk = 0; nk < 16; nk++) {
            float4 sv = *(const float4*)&sST[nk][tx * 4];
            float4 c0 = *(const float4*)&sCT[nk][ty * 8];
            float4 c1 = *(const float4*)&sCT[nk][ty * 8 + 4];
            float cv[8] = {c0.x, c0.y, c0.z, c0.w, c1.x, c1.y, c1.z, c1.w};
#pragma unroll
            for (int i = 0; i < 8; i++) {
                acc[i][0] += cv[i] * sv.x; acc[i][1] += cv[i] * sv.y;
                acc[i][2] += cv[i] * sv.z; acc[i][3] += cv[i] * sv.w;
            }
        }
        __syncthreads();
    }
    float Dh = Dv[h];
    float* Yp = g_Yd + ((size_t)(dir * L + c * CHK)) * DIN + h * HD;
#pragma unroll
    for (int i = 0; i < 8; i++) {
        int l = ty * 8 + i;
        float e = __expf(sAcs[l]);
        int tglob = c * CHK + l;
        int ts = dir ? (L - 1 - tglob) : tglob;
        const float* xrow = g_xc + (size_t)ts * CONVD + h * HD;
#pragma unroll
        for (int j = 0; j < 4; j++) {
            int p = tx * 4 + j;
            size_t o = (size_t)l * DIN + p;
            Yp[o] = Yp[o] + e * acc[i][j] + xrow[p] * Dh;
        }
    }
}

// ---------------- fd = x_og @ fc_D_w^T + D, tiled (32 t-rows per block) ----------------
__global__ __launch_bounds__(256) void fcD_kernel(const float* __restrict__ W,
                                                  const float* __restrict__ Dv) {
    int t0 = blockIdx.x * 32;
    __shared__ float sx[32][132];
    __shared__ float sW[32][132];
    int tid = threadIdx.x;
    int tx = tid & 15, ty = tid >> 4;
    float acc[2][2] = {};
    for (int kc = 0; kc < DIN; kc += 128) {
#pragma unroll
        for (int i = 0; i < 4; i++) {
            int u = tid + i * 256;
            int r = u >> 5, k4 = (u & 31) * 4;
            *(float4*)&sx[r][k4] = *(const float4*)(g_xc + (size_t)(t0 + r) * CONVD + kc + k4);
            *(float4*)&sW[r][k4] = *(const float4*)(W + (size_t)r * DIN + kc + k4);
        }
        __syncthreads();
#pragma unroll 8
        for (int k4 = 0; k4 < 128; k4 += 4) {
            float4 x0 = *(float4*)&sx[ty * 2][k4];
            float4 x1 = *(float4*)&sx[ty * 2 + 1][k4];
            float4 w0 = *(float4*)&sW[tx * 2][k4];
            float4 w1 = *(float4*)&sW[tx * 2 + 1][k4];
            acc[0][0] += x0.x * w0.x + x0.y * w0.y + x0.z * w0.z + x0.w * w0.w;
            acc[0][1] += x0.x * w1.x + x0.y * w1.y + x0.z * w1.z + x0.w * w1.w;
            acc[1][0] += x1.x * w0.x + x1.y * w0.y + x1.z * w0.z + x1.w * w0.w;
            acc[1][1] += x1.x * w1.x + x1.y * w1.y + x1.z * w1.z + x1.w * w1.w;
        }
        __syncthreads();
    }
#pragma unroll
    for (int i = 0; i < 2; i++)
#pragma unroll
        for (int j = 0; j < 2; j++)
            g_fd[(t0 + ty * 2 + i) * NH + tx * 2 + j] = acc[i][j] + Dv[tx * 2 + j];
}

// ---------------- shift + merge dirs + skip + gate + RMSNorm -> fp16 hi/lo ----------------
__global__ void combine_kernel(const float* __restrict__ norm_w) {
    int t = blockIdx.x;
    int tid = threadIdx.x;
    __shared__ float red[256];
    __shared__ float sc;
    float yg[8];
    float ss = 0.f;
#pragma unroll
    for (int k = 0; k < 8; k++) {
        int d = tid + k * 256;
        float yfw = (t > 0) ? g_Yd[((size_t)(t - 1)) * DIN + d] : 0.f;
        float ybw = (t < L - 1) ? g_Yd[((size_t)(L + (L - 2 - t))) * DIN + d] : 0.f;
        float x = g_xc[(size_t)t * CONVD + d];
        float fdv = g_fd[t * NH + (d >> 6)];
        float z = g_zx[(size_t)t * DPROJ + d];
        float v = (yfw + ybw + x * fdv) * (z * sigmoidf_(z));
        yg[k] = v;
        ss += v * v;
    }
    red[tid] = ss;
    __syncthreads();
    for (int o = 128; o > 0; o >>= 1) {
        if (tid < o) red[tid] += red[tid + o];
        __syncthreads();
    }
    if (tid == 0) sc = rsqrtf(red[0] * (1.f / DIN) + EPSV);
    __syncthreads();
    float s = sc;
#pragma unroll
    for (int k = 0; k < 8; k++) {
        int d = tid + k * 256;
        float v = yg[k] * s * norm_w[d];
        __half hv, lv;
        split_hilo_h(v, hv, lv);
        g_ynh[(size_t)t * DIN + d] = hv;
        g_ynl[(size_t)t * DIN + d] = lv;
    }
}

extern "C" void kernel_launch(void* const* d_in, const int* in_sizes, int n_in,
                              void* d_out, int out_size) {
    const float* u          = (const float*)d_in[0];
    const float* in_proj_w  = (const float*)d_in[1];
    const float* conv_w     = (const float*)d_in[2];
    const float* conv_b     = (const float*)d_in[3];
    const float* dt_bias    = (const float*)d_in[4];
    const float* A_log      = (const float*)d_in[5];
    const float* Dv         = (const float*)d_in[6];
    const float* fc_D_w     = (const float*)d_in[7];
    const float* norm_w     = (const float*)d_in[8];
    const float* out_proj_w = (const float*)d_in[9];
    float* out = (float*)d_out;

    float *zx, *Bm, *Cm, *G;
    __half *uh, *ul, *wi, *ynh, *ynl, *wo;
    cudaGetSymbolAddress((void**)&zx, g_zx);
    cudaGetSymbolAddress((void**)&Bm, g_Bm);
    cudaGetSymbolAddress((void**)&Cm, g_Cm);
    cudaGetSymbolAddress((void**)&G, g_G);
    cudaGetSymbolAddress((void**)&uh, g_uh);
    cudaGetSymbolAddress((void**)&ul, g_ul);
    cudaGetSymbolAddress((void**)&wi, g_wi);
    cudaGetSymbolAddress((void**)&ynh, g_ynh);
    cudaGetSymbolAddress((void**)&ynl, g_ynl);
    cudaGetSymbolAddress((void**)&wo, g_wo);

    const int smemB = 2 * 3 * 128 * APAD * 2;  // 61440 B
    cudaFuncSetAttribute(gemm_2t, cudaFuncAttributeMaxDynamicSharedMemorySize, smemB);

    // 0) convert: activations fp16 hi/lo, weights single fp16
    cvt_hilo_kernel<<<((size_t)L * DM + 255) / 256, 256>>>(u, uh, ul, (size_t)L * DM);
    cvt_h_kernel<<<((size_t)DPROJ * DM + 255) / 256, 256>>>(in_proj_w, wi, (size_t)DPROJ * DM);
    cvt_h_kernel<<<((size_t)DM * DIN + 255) / 256, 256>>>(out_proj_w, wo, (size_t)DM * DIN);

    // 1) in_proj
    gemm_2t<<<dim3((DPROJ + 127) / 128, L / 128), 256, smemB>>>(uh, ul, wi, zx, DPROJ, DM);
    // 2) conv + silu
    conv_kernel<<<((size_t)L * CONVD + 255) / 256, 256>>>(conv_w, conv_b);
    // 3) dt softplus
    dt_kernel<<<(2 * L * NH + 255) / 256, 256>>>(dt_bias);
    // 4) B/C prep
    prep_bc_kernel<<<(2 * L * NST + 255) / 256, 256>>>();
    // 5) per-chunk cumsum of A*dt
    acs_kernel<<<dim3(NC, 2), 32>>>(A_log);
    // 6) G = C B^T per (dir,chunk), 64x64 tiles (full-chip)
    sgemm64_nt<<<dim3(2, 2, 2 * NC), 256>>>(Cm, Bm, G);
    // 7) Y_diag + chunk states (vectorized smem)
    ydiag_states_kernel<<<2 * NC * NH, 256>>>();
    // 8) inter-chunk recurrence
    recur_kernel<<<512, 256>>>();
    // 9) Y_off + x*D (vectorized smem)
    yoff_kernel<<<2 * NC * NH, 256>>>(Dv);
    // 10) fd
    fcD_kernel<<<L / 32, 256>>>(fc_D_w, Dv);
    // 11) shift/merge/gate/RMSNorm
    combine_kernel<<<L, 256>>>(norm_w);
    // 12) out_proj
    gemm_2t<<<dim3(DM / 128, L / 128), 256, smemB>>>(ynh, ynl, wo, out, DM, DIN);
}